// round 2
// baseline (speedup 1.0000x reference)
#include <cuda_runtime.h>

#define DM 1024
#define NH 16
#define DKH 64
#define B_ 2
#define S_ 2048
#define MR (B_*S_)   // 4096 rows

// Scratch (allocation-free rule: device globals)
__device__ float g_q[MR*DM];
__device__ float g_k[MR*DM];
__device__ float g_v[MR*DM];
__device__ float g_c[MR*DM];

// ---------------------------------------------------------------------------
// GEMM: C[M,N] = A[M,K] @ W[N,K]^T + bias[N]
// BM=128, BN=64, BK=16, 256 threads, 8x4 micro-tile.
// Smem stored K-major (transposed) so inner loop is pure float4 LDS + FMA.
// ---------------------------------------------------------------------------
__global__ __launch_bounds__(256) void gemm_tn_bias(
    const float* __restrict__ A, const float* __restrict__ W,
    const float* __restrict__ bias, float* __restrict__ C,
    int M, int N, int K)
{
    constexpr int BM = 128, BN = 64, BK = 16;
    constexpr int AST = BM + 4;   // 132: k-major row stride (16B-aligned, low conflict)
    constexpr int BST = BN + 4;   // 68
    __shared__ float As[BK * AST];
    __shared__ float Bs[BK * BST];

    const int tid = threadIdx.x;
    const int tx = tid & 15;        // over N (16 * 4 = 64)
    const int ty = tid >> 4;        // over M (16 * 8 = 128)
    const int m0 = blockIdx.y * BM;
    const int n0 = blockIdx.x * BN;

    const int lrow = tid >> 2;          // 0..63
    const int lk4  = (tid & 3) * 4;     // 0,4,8,12

    const float* Ag0 = A + (size_t)(m0 + lrow) * K + lk4;
    const float* Ag1 = Ag0 + (size_t)64 * K;
    const float* Wg  = W + (size_t)(n0 + lrow) * K + lk4;

    float4 ra0 = *(const float4*)Ag0;
    float4 ra1 = *(const float4*)Ag1;
    float4 rb  = *(const float4*)Wg;

    float acc[8][4];
    #pragma unroll
    for (int i = 0; i < 8; i++)
        #pragma unroll
        for (int j = 0; j < 4; j++) acc[i][j] = 0.0f;

    const int nt = K / BK;
    for (int kt = 0; kt < nt; ++kt) {
        __syncthreads();
        // store current tile transposed into smem
        As[(lk4+0)*AST + lrow] = ra0.x;
        As[(lk4+1)*AST + lrow] = ra0.y;
        As[(lk4+2)*AST + lrow] = ra0.z;
        As[(lk4+3)*AST + lrow] = ra0.w;
        As[(lk4+0)*AST + lrow + 64] = ra1.x;
        As[(lk4+1)*AST + lrow + 64] = ra1.y;
        As[(lk4+2)*AST + lrow + 64] = ra1.z;
        As[(lk4+3)*AST + lrow + 64] = ra1.w;
        Bs[(lk4+0)*BST + lrow] = rb.x;
        Bs[(lk4+1)*BST + lrow] = rb.y;
        Bs[(lk4+2)*BST + lrow] = rb.z;
        Bs[(lk4+3)*BST + lrow] = rb.w;
        __syncthreads();

        // prefetch next tile into registers (overlaps with compute)
        if (kt + 1 < nt) {
            const int off = (kt + 1) * BK;
            ra0 = *(const float4*)(Ag0 + off);
            ra1 = *(const float4*)(Ag1 + off);
            rb  = *(const float4*)(Wg  + off);
        }

        #pragma unroll
        for (int kk = 0; kk < BK; ++kk) {
            float4 a0 = *(const float4*)&As[kk*AST + ty*8];
            float4 a1 = *(const float4*)&As[kk*AST + ty*8 + 4];
            float4 b0 = *(const float4*)&Bs[kk*BST + tx*4];
            float ar[8] = {a0.x, a0.y, a0.z, a0.w, a1.x, a1.y, a1.z, a1.w};
            float br[4] = {b0.x, b0.y, b0.z, b0.w};
            #pragma unroll
            for (int i = 0; i < 8; i++)
                #pragma unroll
                for (int j = 0; j < 4; j++)
                    acc[i][j] += ar[i] * br[j];
        }
    }

    float4 bb = *(const float4*)&bias[n0 + tx*4];
    #pragma unroll
    for (int i = 0; i < 8; i++) {
        float4 o;
        o.x = acc[i][0] + bb.x;
        o.y = acc[i][1] + bb.y;
        o.z = acc[i][2] + bb.z;
        o.w = acc[i][3] + bb.w;
        *(float4*)&C[(size_t)(m0 + ty*8 + i) * N + n0 + tx*4] = o;
    }
}

// ---------------------------------------------------------------------------
// Flash attention: one block per (64-query tile, b*h).
// Q,K stored d-major in smem (float4 loads); V k-major; P via smem transpose.
// Scale 1/sqrt(64) folded into Q. Online softmax.
// ---------------------------------------------------------------------------
__global__ __launch_bounds__(256) void attn_kernel(const int* __restrict__ mask)
{
    constexpr int QST = 68, KST = 68, VST = 68, PST = 65;
    extern __shared__ float sm[];
    float* Qs = sm;                 // [d][q]
    float* Ks = Qs + 64 * QST;      // [d][k]
    float* Vs = Ks + 64 * KST;      // [k][d]
    float* Ps = Vs + 64 * VST;      // [k][q]
    __shared__ int msk[64];

    const int tid = threadIdx.x;
    const int tx = tid & 15;        // over keys/dims (16*4=64)
    const int ty = tid >> 4;        // over queries (16*4=64)
    const int bh = blockIdx.y;
    const int b = bh >> 4;
    const int h = bh & 15;
    const int q0 = blockIdx.x * 64;

    const int ldr = tid >> 2;            // 0..63 (row within tile for loads)
    const int lc4 = (tid & 3) * 16;      // 16 dims per thread group

    const float scale = 0.125f;          // 1/sqrt(64)

    // Load Q tile transposed (d-major), pre-scaled
    {
        const float* Qg = g_q + ((size_t)(b*S_ + q0 + ldr)) * DM + h*DKH + lc4;
        #pragma unroll
        for (int u = 0; u < 4; u++) {
            float4 v = *(const float4*)(Qg + u*4);
            int d = lc4 + u*4;
            Qs[(d+0)*QST + ldr] = v.x * scale;
            Qs[(d+1)*QST + ldr] = v.y * scale;
            Qs[(d+2)*QST + ldr] = v.z * scale;
            Qs[(d+3)*QST + ldr] = v.w * scale;
        }
    }

    float o[4][4];
    float mrow[4], lsum[4];
    #pragma unroll
    for (int i = 0; i < 4; i++) {
        mrow[i] = -1e30f;
        lsum[i] = 0.0f;
        #pragma unroll
        for (int j = 0; j < 4; j++) o[i][j] = 0.0f;
    }

    for (int t = 0; t < S_/64; ++t) {
        const int k0 = t * 64;
        __syncthreads();    // protects Ks/Vs (prev PV read) and Ps rewrite
        {
            const float* Kg = g_k + ((size_t)(b*S_ + k0 + ldr)) * DM + h*DKH + lc4;
            const float* Vg = g_v + ((size_t)(b*S_ + k0 + ldr)) * DM + h*DKH + lc4;
            #pragma unroll
            for (int u = 0; u < 4; u++) {
                int d = lc4 + u*4;
                float4 kv = *(const float4*)(Kg + u*4);
                Ks[(d+0)*KST + ldr] = kv.x;
                Ks[(d+1)*KST + ldr] = kv.y;
                Ks[(d+2)*KST + ldr] = kv.z;
                Ks[(d+3)*KST + ldr] = kv.w;
                float4 vv = *(const float4*)(Vg + u*4);
                *(float4*)&Vs[ldr*VST + d] = vv;
            }
        }
        if (tid < 64) msk[tid] = mask[b*S_ + k0 + tid];
        __syncthreads();

        // S = Q @ K^T  (contraction over d)
        float s[4][4];
        #pragma unroll
        for (int i = 0; i < 4; i++)
            #pragma unroll
            for (int j = 0; j < 4; j++) s[i][j] = 0.0f;

        #pragma unroll 8
        for (int d = 0; d < 64; ++d) {
            float4 qa = *(const float4*)&Qs[d*QST + ty*4];
            float4 kb = *(const float4*)&Ks[d*KST + tx*4];
            float aq[4] = {qa.x, qa.y, qa.z, qa.w};
            float bk[4] = {kb.x, kb.y, kb.z, kb.w};
            #pragma unroll
            for (int i = 0; i < 4; i++)
                #pragma unroll
                for (int j = 0; j < 4; j++)
                    s[i][j] += aq[i] * bk[j];
        }

        // mask
        #pragma unroll
        for (int j = 0; j < 4; j++) {
            if (msk[tx*4 + j] == 0) {
                #pragma unroll
                for (int i = 0; i < 4; i++) s[i][j] = -1e9f;
            }
        }

        // online softmax (row = query; reduce across the 16 tx threads)
        #pragma unroll
        for (int i = 0; i < 4; i++) {
            float mx = fmaxf(fmaxf(s[i][0], s[i][1]), fmaxf(s[i][2], s[i][3]));
            #pragma unroll
            for (int off = 8; off >= 1; off >>= 1)
                mx = fmaxf(mx, __shfl_xor_sync(0xffffffffu, mx, off, 16));
            float mn = fmaxf(mrow[i], mx);
            float corr = __expf(mrow[i] - mn);
            float rs = 0.0f;
            #pragma unroll
            for (int j = 0; j < 4; j++) {
                float p = __expf(s[i][j] - mn);
                s[i][j] = p;
                rs += p;
            }
            #pragma unroll
            for (int off = 8; off >= 1; off >>= 1)
                rs += __shfl_xor_sync(0xffffffffu, rs, off, 16);
            lsum[i] = lsum[i] * corr + rs;
            mrow[i] = mn;
            #pragma unroll
            for (int j = 0; j < 4; j++) o[i][j] *= corr;
        }

        // write P transposed: Ps[k][q]
        #pragma unroll
        for (int j = 0; j < 4; j++)
            #pragma unroll
            for (int i = 0; i < 4; i++)
                Ps[(tx*4 + j)*PST + ty*4 + i] = s[i][j];
        __syncthreads();

        // O += P @ V   (contraction over k)
        #pragma unroll 8
        for (int kk = 0; kk < 64; ++kk) {
            float4 vb = *(const float4*)&Vs[kk*VST + tx*4];
            float pa[4];
            #pragma unroll
            for (int i = 0; i < 4; i++) pa[i] = Ps[kk*PST + ty*4 + i];
            float bv[4] = {vb.x, vb.y, vb.z, vb.w};
            #pragma unroll
            for (int i = 0; i < 4; i++)
                #pragma unroll
                for (int j = 0; j < 4; j++)
                    o[i][j] += pa[i] * bv[j];
        }
    }

    // epilogue: normalize, write ctx[b, q, h*64+d]
    #pragma unroll
    for (int i = 0; i < 4; i++) {
        float inv = 1.0f / lsum[i];
        float4 ov;
        ov.x = o[i][0] * inv;
        ov.y = o[i][1] * inv;
        ov.z = o[i][2] * inv;
        ov.w = o[i][3] * inv;
        *(float4*)&g_c[((size_t)(b*S_ + q0 + ty*4 + i)) * DM + h*DKH + tx*4] = ov;
    }
}

// ---------------------------------------------------------------------------
extern "C" void kernel_launch(void* const* d_in, const int* in_sizes, int n_in,
                              void* d_out, int out_size)
{
    const float* q    = (const float*)d_in[0];
    const float* k    = (const float*)d_in[1];
    const float* v    = (const float*)d_in[2];
    const int*   mask = (const int*)  d_in[3];
    const float* Wq   = (const float*)d_in[4];
    const float* bq   = (const float*)d_in[5];
    const float* Wk   = (const float*)d_in[6];
    const float* bk   = (const float*)d_in[7];
    const float* Wv   = (const float*)d_in[8];
    const float* bv   = (const float*)d_in[9];
    const float* Wo   = (const float*)d_in[10];
    const float* bo   = (const float*)d_in[11];
    float* out = (float*)d_out;

    float *pq, *pk, *pv, *pc;
    cudaGetSymbolAddress((void**)&pq, g_q);
    cudaGetSymbolAddress((void**)&pk, g_k);
    cudaGetSymbolAddress((void**)&pv, g_v);
    cudaGetSymbolAddress((void**)&pc, g_c);

    const dim3 gg(DM/64, MR/128);
    const dim3 gb(256);

    gemm_tn_bias<<<gg, gb>>>(q, Wq, bq, pq, MR, DM, DM);
    gemm_tn_bias<<<gg, gb>>>(k, Wk, bk, pk, MR, DM, DM);
    gemm_tn_bias<<<gg, gb>>>(v, Wv, bv, pv, MR, DM, DM);

    const int smem = (64*68*3 + 64*65) * (int)sizeof(float);  // 68864 B
    cudaFuncSetAttribute(attn_kernel, cudaFuncAttributeMaxDynamicSharedMemorySize, smem);
    attn_kernel<<<dim3(S_/64, B_*NH), 256, smem>>>(mask);

    gemm_tn_bias<<<gg, gb>>>(pc, Wo, bo, out, MR, DM, DM);
}

// round 5
// speedup vs baseline: 1.2732x; 1.2732x over previous
#include <cuda_runtime.h>
#include <cuda_bf16.h>
#include <cstdint>

#define DM 1024
#define NH 16
#define DKH 64
#define B_ 2
#define S_ 2048
#define MR (B_*S_)   // 4096 rows

// Scratch (allocation-free rule: device globals)
__device__ float g_q[MR*DM];
__device__ float g_k[MR*DM];
__device__ float g_v[MR*DM];
__device__ float g_c[MR*DM];

// ===========================================================================
// Helpers
// ===========================================================================
__device__ __forceinline__ uint32_t smem_u32(const void* p) {
    uint32_t a;
    asm("{ .reg .u64 t; cvta.to.shared.u64 t, %1; cvt.u32.u64 %0, t; }" : "=r"(a) : "l"(p));
    return a;
}

__device__ __forceinline__ void ldsm4(uint32_t r[4], uint32_t addr) {
    asm volatile("ldmatrix.sync.aligned.m8n8.x4.shared.b16 {%0,%1,%2,%3}, [%4];"
                 : "=r"(r[0]), "=r"(r[1]), "=r"(r[2]), "=r"(r[3]) : "r"(addr));
}

__device__ __forceinline__ void mma16816(float c[4], const uint32_t a[4],
                                         uint32_t b0, uint32_t b1) {
    asm volatile(
        "mma.sync.aligned.m16n8k16.row.col.f32.bf16.bf16.f32 "
        "{%0,%1,%2,%3}, {%4,%5,%6,%7}, {%8,%9}, {%0,%1,%2,%3};"
        : "+f"(c[0]), "+f"(c[1]), "+f"(c[2]), "+f"(c[3])
        : "r"(a[0]), "r"(a[1]), "r"(a[2]), "r"(a[3]), "r"(b0), "r"(b1));
}

// Split fp32 x into bf16 hi + bf16 lo, store 4 values (8 bytes each) to smem.
__device__ __forceinline__ void cvt_split_store(char* hi, char* lo, float4 v) {
    __nv_bfloat16 h0 = __float2bfloat16_rn(v.x);
    __nv_bfloat16 h1 = __float2bfloat16_rn(v.y);
    __nv_bfloat16 h2 = __float2bfloat16_rn(v.z);
    __nv_bfloat16 h3 = __float2bfloat16_rn(v.w);
    float l0 = v.x - __bfloat162float(h0);
    float l1 = v.y - __bfloat162float(h1);
    float l2 = v.z - __bfloat162float(h2);
    float l3 = v.w - __bfloat162float(h3);
    union { __nv_bfloat162 b[2]; uint2 u; } H, L;
    H.b[0] = __halves2bfloat162(h0, h1);
    H.b[1] = __halves2bfloat162(h2, h3);
    L.b[0] = __halves2bfloat162(__float2bfloat16_rn(l0), __float2bfloat16_rn(l1));
    L.b[1] = __halves2bfloat162(__float2bfloat16_rn(l2), __float2bfloat16_rn(l3));
    *(uint2*)hi = H.u;
    *(uint2*)lo = L.u;
}

// ===========================================================================
// HMMA split-bf16 GEMM:  C[M,N] = A[M,K] @ W[N,K]^T + bias[N]
// Block tile 128x64, BK=32 (fp32), 8 warps, warp tile 32x32.
// 3 MMAs per position: Ah*Bh + Ah*Bl + Al*Bh (fp32 accum) -> ~1e-5 rel err.
// smem rows: 32 bf16 = 64B data, padded to 80B stride (conflict-free ldmatrix).
// ===========================================================================
#define RST 80                       // smem row stride in bytes
#define SA_H 0
#define SA_L (128*RST)               // 10240
#define SB_H (2*128*RST)             // 20480
#define SB_L (SB_H + 64*RST)         // 25600
#define GEMM_SMEM (SB_L + 64*RST)    // 30720

__global__ __launch_bounds__(256) void gemm_hmma(
    const float* __restrict__ A, const float* __restrict__ W,
    const float* __restrict__ bias, float* __restrict__ C,
    int M, int N, int K)
{
    __shared__ char sm[GEMM_SMEM];
    const uint32_t sb = smem_u32(sm);

    const int tid  = threadIdx.x;
    const int lane = tid & 31;
    const int wid  = tid >> 5;
    const int wr   = wid >> 1;       // 0..3 : 32-row band
    const int wc   = wid & 1;        // 0..1 : 32-col band
    const int m0   = blockIdx.y * 128;
    const int n0   = blockIdx.x * 64;

    // loader mapping: 32 rows x 8 col-groups (4 floats each) per pass
    const int lrow = tid >> 3;       // 0..31
    const int lcg  = tid & 7;        // 0..7

    // ldmatrix lane addressing (byte offsets within tile)
    const uint32_t a_lane = (uint32_t)((wr*32 + (lane & 15)) * RST + (lane >> 4) * 16);
    const uint32_t b_lane = (uint32_t)((wc*32 + (lane & 7) + ((lane >> 4) & 1) * 8) * RST
                                       + ((lane >> 3) & 1) * 16);

    float acc[2][4][4];
    #pragma unroll
    for (int mi = 0; mi < 2; mi++)
        #pragma unroll
        for (int ni = 0; ni < 4; ni++)
            #pragma unroll
            for (int r = 0; r < 4; r++) acc[mi][ni][r] = 0.0f;

    const int NCH = K / 32;          // 32 chunks
    for (int ch = 0; ch < NCH; ++ch) {
        __syncthreads();
        // ---- load + split-convert A (128x32) and W (64x32) into smem ----
        {
            const float* a = A + (size_t)(m0 + lrow) * K + ch*32 + lcg*4;
            #pragma unroll
            for (int it = 0; it < 4; ++it) {
                int r = lrow + it*32;
                float4 av = *(const float4*)(a + (size_t)it * 32 * K);
                cvt_split_store(sm + SA_H + r*RST + lcg*8,
                                sm + SA_L + r*RST + lcg*8, av);
            }
            const float* w = W + (size_t)(n0 + lrow) * K + ch*32 + lcg*4;
            #pragma unroll
            for (int it = 0; it < 2; ++it) {
                int r = lrow + it*32;
                float4 wv = *(const float4*)(w + (size_t)it * 32 * K);
                cvt_split_store(sm + SB_H + r*RST + lcg*8,
                                sm + SB_L + r*RST + lcg*8, wv);
            }
        }
        __syncthreads();

        // ---- 2 x k16 steps of MMAs ----
        #pragma unroll
        for (int ks = 0; ks < 2; ++ks) {
            uint32_t ah[2][4], al[2][4], bh[2][4], bl[2][4];
            #pragma unroll
            for (int mi = 0; mi < 2; ++mi) {
                ldsm4(ah[mi], sb + SA_H + mi*16*RST + ks*32 + a_lane);
                ldsm4(al[mi], sb + SA_L + mi*16*RST + ks*32 + a_lane);
            }
            #pragma unroll
            for (int j2 = 0; j2 < 2; ++j2) {
                ldsm4(bh[j2], sb + SB_H + j2*16*RST + ks*32 + b_lane);
                ldsm4(bl[j2], sb + SB_L + j2*16*RST + ks*32 + b_lane);
            }
            #pragma unroll
            for (int mi = 0; mi < 2; ++mi)
                #pragma unroll
                for (int j2 = 0; j2 < 2; ++j2)
                    #pragma unroll
                    for (int sub = 0; sub < 2; ++sub) {
                        int ni = j2*2 + sub;
                        mma16816(acc[mi][ni], ah[mi], bh[j2][sub*2], bh[j2][sub*2+1]);
                        mma16816(acc[mi][ni], ah[mi], bl[j2][sub*2], bl[j2][sub*2+1]);
                        mma16816(acc[mi][ni], al[mi], bh[j2][sub*2], bh[j2][sub*2+1]);
                    }
        }
    }

    // ---- epilogue: add bias, store fp32 ----
    #pragma unroll
    for (int mi = 0; mi < 2; ++mi) {
        int r = m0 + wr*32 + mi*16 + (lane >> 2);
        #pragma unroll
        for (int ni = 0; ni < 4; ++ni) {
            int ccol = n0 + wc*32 + ni*8 + (lane & 3) * 2;
            float2 bb = *(const float2*)&bias[ccol];
            float2 o0, o1;
            o0.x = acc[mi][ni][0] + bb.x;
            o0.y = acc[mi][ni][1] + bb.y;
            o1.x = acc[mi][ni][2] + bb.x;
            o1.y = acc[mi][ni][3] + bb.y;
            *(float2*)&C[(size_t)r * N + ccol] = o0;
            *(float2*)&C[(size_t)(r + 8) * N + ccol] = o1;
        }
    }
}

// ---------------------------------------------------------------------------
// Flash attention (R2-passing version): one block per (64-query tile, b*h).
// ---------------------------------------------------------------------------
__global__ __launch_bounds__(256) void attn_kernel(const int* __restrict__ mask)
{
    constexpr int QST = 68, KST = 68, VST = 68, PST = 65;
    extern __shared__ float smf[];
    float* Qs = smf;
    float* Ks = Qs + 64 * QST;
    float* Vs = Ks + 64 * KST;
    float* Ps = Vs + 64 * VST;
    __shared__ int msk[64];

    const int tid = threadIdx.x;
    const int tx = tid & 15;
    const int ty = tid >> 4;
    const int bh = blockIdx.y;
    const int b = bh >> 4;
    const int h = bh & 15;
    const int q0 = blockIdx.x * 64;

    const int ldr = tid >> 2;
    const int lc4 = (tid & 3) * 16;

    const float scale = 0.125f;

    {
        const float* Qg = g_q + ((size_t)(b*S_ + q0 + ldr)) * DM + h*DKH + lc4;
        #pragma unroll
        for (int u = 0; u < 4; u++) {
            float4 v = *(const float4*)(Qg + u*4);
            int d = lc4 + u*4;
            Qs[(d+0)*QST + ldr] = v.x * scale;
            Qs[(d+1)*QST + ldr] = v.y * scale;
            Qs[(d+2)*QST + ldr] = v.z * scale;
            Qs[(d+3)*QST + ldr] = v.w * scale;
        }
    }

    float o[4][4];
    float mrow[4], lsum[4];
    #pragma unroll
    for (int i = 0; i < 4; i++) {
        mrow[i] = -1e30f;
        lsum[i] = 0.0f;
        #pragma unroll
        for (int j = 0; j < 4; j++) o[i][j] = 0.0f;
    }

    for (int t = 0; t < S_/64; ++t) {
        const int k0 = t * 64;
        __syncthreads();
        {
            const float* Kg = g_k + ((size_t)(b*S_ + k0 + ldr)) * DM + h*DKH + lc4;
            const float* Vg = g_v + ((size_t)(b*S_ + k0 + ldr)) * DM + h*DKH + lc4;
            #pragma unroll
            for (int u = 0; u < 4; u++) {
                int d = lc4 + u*4;
                float4 kv = *(const float4*)(Kg + u*4);
                Ks[(d+0)*KST + ldr] = kv.x;
                Ks[(d+1)*KST + ldr] = kv.y;
                Ks[(d+2)*KST + ldr] = kv.z;
                Ks[(d+3)*KST + ldr] = kv.w;
                float4 vv = *(const float4*)(Vg + u*4);
                *(float4*)&Vs[ldr*VST + d] = vv;
            }
        }
        if (tid < 64) msk[tid] = mask[b*S_ + k0 + tid];
        __syncthreads();

        float s[4][4];
        #pragma unroll
        for (int i = 0; i < 4; i++)
            #pragma unroll
            for (int j = 0; j < 4; j++) s[i][j] = 0.0f;

        #pragma unroll 8
        for (int d = 0; d < 64; ++d) {
            float4 qa = *(const float4*)&Qs[d*QST + ty*4];
            float4 kb = *(const float4*)&Ks[d*KST + tx*4];
            float aq[4] = {qa.x, qa.y, qa.z, qa.w};
            float bk[4] = {kb.x, kb.y, kb.z, kb.w};
            #pragma unroll
            for (int i = 0; i < 4; i++)
                #pragma unroll
                for (int j = 0; j < 4; j++)
                    s[i][j] += aq[i] * bk[j];
        }

        #pragma unroll
        for (int j = 0; j < 4; j++) {
            if (msk[tx*4 + j] == 0) {
                #pragma unroll
                for (int i = 0; i < 4; i++) s[i][j] = -1e9f;
            }
        }

        #pragma unroll
        for (int i = 0; i < 4; i++) {
            float mx = fmaxf(fmaxf(s[i][0], s[i][1]), fmaxf(s[i][2], s[i][3]));
            #pragma unroll
            for (int off = 8; off >= 1; off >>= 1)
                mx = fmaxf(mx, __shfl_xor_sync(0xffffffffu, mx, off, 16));
            float mn = fmaxf(mrow[i], mx);
            float corr = __expf(mrow[i] - mn);
            float rs = 0.0f;
            #pragma unroll
            for (int j = 0; j < 4; j++) {
                float p = __expf(s[i][j] - mn);
                s[i][j] = p;
                rs += p;
            }
            #pragma unroll
            for (int off = 8; off >= 1; off >>= 1)
                rs += __shfl_xor_sync(0xffffffffu, rs, off, 16);
            lsum[i] = lsum[i] * corr + rs;
            mrow[i] = mn;
            #pragma unroll
            for (int j = 0; j < 4; j++) o[i][j] *= corr;
        }

        #pragma unroll
        for (int j = 0; j < 4; j++)
            #pragma unroll
            for (int i = 0; i < 4; i++)
                Ps[(tx*4 + j)*PST + ty*4 + i] = s[i][j];
        __syncthreads();

        #pragma unroll 8
        for (int kk = 0; kk < 64; ++kk) {
            float4 vb = *(const float4*)&Vs[kk*VST + tx*4];
            float pa[4];
            #pragma unroll
            for (int i = 0; i < 4; i++) pa[i] = Ps[kk*PST + ty*4 + i];
            float bv[4] = {vb.x, vb.y, vb.z, vb.w};
            #pragma unroll
            for (int i = 0; i < 4; i++)
                #pragma unroll
                for (int j = 0; j < 4; j++)
                    o[i][j] += pa[i] * bv[j];
        }
    }

    #pragma unroll
    for (int i = 0; i < 4; i++) {
        float inv = 1.0f / lsum[i];
        float4 ov;
        ov.x = o[i][0] * inv;
        ov.y = o[i][1] * inv;
        ov.z = o[i][2] * inv;
        ov.w = o[i][3] * inv;
        *(float4*)&g_c[((size_t)(b*S_ + q0 + ty*4 + i)) * DM + h*DKH + tx*4] = ov;
    }
}

// ---------------------------------------------------------------------------
extern "C" void kernel_launch(void* const* d_in, const int* in_sizes, int n_in,
                              void* d_out, int out_size)
{
    const float* q    = (const float*)d_in[0];
    const float* k    = (const float*)d_in[1];
    const float* v    = (const float*)d_in[2];
    const int*   mask = (const int*)  d_in[3];
    const float* Wq   = (const float*)d_in[4];
    const float* bq   = (const float*)d_in[5];
    const float* Wk   = (const float*)d_in[6];
    const float* bk   = (const float*)d_in[7];
    const float* Wv   = (const float*)d_in[8];
    const float* bv   = (const float*)d_in[9];
    const float* Wo   = (const float*)d_in[10];
    const float* bo   = (const float*)d_in[11];
    float* out = (float*)d_out;

    float *pq, *pk, *pv, *pc;
    cudaGetSymbolAddress((void**)&pq, g_q);
    cudaGetSymbolAddress((void**)&pk, g_k);
    cudaGetSymbolAddress((void**)&pv, g_v);
    cudaGetSymbolAddress((void**)&pc, g_c);

    const int asmem = (64*68*3 + 64*65) * (int)sizeof(float);  // 68864 B
    cudaFuncSetAttribute(attn_kernel, cudaFuncAttributeMaxDynamicSharedMemorySize, asmem);

    const dim3 gg(DM/64, MR/128);   // (16, 32)
    gemm_hmma<<<gg, 256>>>(q, Wq, bq, pq, MR, DM, DM);
    gemm_hmma<<<gg, 256>>>(k, Wk, bk, pk, MR, DM, DM);
    gemm_hmma<<<gg, 256>>>(v, Wv, bv, pv, MR, DM, DM);

    attn_kernel<<<dim3(S_/64, B_*NH), 256, asmem>>>(mask);

    gemm_hmma<<<gg, 256>>>(pc, Wo, bo, out, MR, DM, DM);
}

// round 6
// speedup vs baseline: 2.3133x; 1.8168x over previous
#include <cuda_runtime.h>
#include <cuda_bf16.h>
#include <cstdint>

#define DM 1024
#define NH 16
#define DKH 64
#define B_ 2
#define S_ 2048
#define MR (B_*S_)   // 4096 rows

// Scratch (allocation-free rule: device globals)
__device__ float g_q[MR*DM];
__device__ float g_k[MR*DM];
__device__ float g_v[MR*DM];
__device__ float g_c[MR*DM];

// ===========================================================================
// Helpers
// ===========================================================================
__device__ __forceinline__ uint32_t smem_u32(const void* p) {
    uint32_t a;
    asm("{ .reg .u64 t; cvta.to.shared.u64 t, %1; cvt.u32.u64 %0, t; }" : "=r"(a) : "l"(p));
    return a;
}

__device__ __forceinline__ void ldsm4(uint32_t r[4], uint32_t addr) {
    asm volatile("ldmatrix.sync.aligned.m8n8.x4.shared.b16 {%0,%1,%2,%3}, [%4];"
                 : "=r"(r[0]), "=r"(r[1]), "=r"(r[2]), "=r"(r[3]) : "r"(addr));
}
__device__ __forceinline__ void ldsm4t(uint32_t r[4], uint32_t addr) {
    asm volatile("ldmatrix.sync.aligned.m8n8.x4.trans.shared.b16 {%0,%1,%2,%3}, [%4];"
                 : "=r"(r[0]), "=r"(r[1]), "=r"(r[2]), "=r"(r[3]) : "r"(addr));
}

__device__ __forceinline__ void mma16816(float c[4], const uint32_t a[4],
                                         uint32_t b0, uint32_t b1) {
    asm volatile(
        "mma.sync.aligned.m16n8k16.row.col.f32.bf16.bf16.f32 "
        "{%0,%1,%2,%3}, {%4,%5,%6,%7}, {%8,%9}, {%0,%1,%2,%3};"
        : "+f"(c[0]), "+f"(c[1]), "+f"(c[2]), "+f"(c[3])
        : "r"(a[0]), "r"(a[1]), "r"(a[2]), "r"(a[3]), "r"(b0), "r"(b1));
}

// Split fp32 x into bf16 hi + bf16 lo, store 4 values (8 bytes each) to smem.
__device__ __forceinline__ void cvt_split_store(char* hi, char* lo, float4 v) {
    __nv_bfloat16 h0 = __float2bfloat16_rn(v.x);
    __nv_bfloat16 h1 = __float2bfloat16_rn(v.y);
    __nv_bfloat16 h2 = __float2bfloat16_rn(v.z);
    __nv_bfloat16 h3 = __float2bfloat16_rn(v.w);
    float l0 = v.x - __bfloat162float(h0);
    float l1 = v.y - __bfloat162float(h1);
    float l2 = v.z - __bfloat162float(h2);
    float l3 = v.w - __bfloat162float(h3);
    union { __nv_bfloat162 b[2]; uint2 u; } H, L;
    H.b[0] = __halves2bfloat162(h0, h1);
    H.b[1] = __halves2bfloat162(h2, h3);
    L.b[0] = __halves2bfloat162(__float2bfloat16_rn(l0), __float2bfloat16_rn(l1));
    L.b[1] = __halves2bfloat162(__float2bfloat16_rn(l2), __float2bfloat16_rn(l3));
    *(uint2*)hi = H.u;
    *(uint2*)lo = L.u;
}

// Pack two fp32 into bf16x2 hi + bf16x2 lo (register form)
__device__ __forceinline__ void pack_split(float e, float o2, uint32_t& hi, uint32_t& lo) {
    __nv_bfloat162 H = __floats2bfloat162_rn(e, o2);
    float re = e - __low2float(H);
    float ro = o2 - __high2float(H);
    __nv_bfloat162 L = __floats2bfloat162_rn(re, ro);
    hi = reinterpret_cast<uint32_t&>(H);
    lo = reinterpret_cast<uint32_t&>(L);
}

// ===========================================================================
// HMMA split-bf16 GEMM:  C[M,N] = A[M,K] @ W[N,K]^T + bias[N]   (R5, passing)
// ===========================================================================
#define RST 80
#define SA_H 0
#define SA_L (128*RST)
#define SB_H (2*128*RST)
#define SB_L (SB_H + 64*RST)
#define GEMM_SMEM (SB_L + 64*RST)

__global__ __launch_bounds__(256) void gemm_hmma(
    const float* __restrict__ A, const float* __restrict__ W,
    const float* __restrict__ bias, float* __restrict__ C,
    int M, int N, int K)
{
    __shared__ char sm[GEMM_SMEM];
    const uint32_t sb = smem_u32(sm);

    const int tid  = threadIdx.x;
    const int lane = tid & 31;
    const int wid  = tid >> 5;
    const int wr   = wid >> 1;
    const int wc   = wid & 1;
    const int m0   = blockIdx.y * 128;
    const int n0   = blockIdx.x * 64;

    const int lrow = tid >> 3;
    const int lcg  = tid & 7;

    const uint32_t a_lane = (uint32_t)((wr*32 + (lane & 15)) * RST + (lane >> 4) * 16);
    const uint32_t b_lane = (uint32_t)((wc*32 + (lane & 7) + ((lane >> 4) & 1) * 8) * RST
                                       + ((lane >> 3) & 1) * 16);

    float acc[2][4][4];
    #pragma unroll
    for (int mi = 0; mi < 2; mi++)
        #pragma unroll
        for (int ni = 0; ni < 4; ni++)
            #pragma unroll
            for (int r = 0; r < 4; r++) acc[mi][ni][r] = 0.0f;

    const int NCH = K / 32;
    for (int ch = 0; ch < NCH; ++ch) {
        __syncthreads();
        {
            const float* a = A + (size_t)(m0 + lrow) * K + ch*32 + lcg*4;
            #pragma unroll
            for (int it = 0; it < 4; ++it) {
                int r = lrow + it*32;
                float4 av = *(const float4*)(a + (size_t)it * 32 * K);
                cvt_split_store(sm + SA_H + r*RST + lcg*8,
                                sm + SA_L + r*RST + lcg*8, av);
            }
            const float* w = W + (size_t)(n0 + lrow) * K + ch*32 + lcg*4;
            #pragma unroll
            for (int it = 0; it < 2; ++it) {
                int r = lrow + it*32;
                float4 wv = *(const float4*)(w + (size_t)it * 32 * K);
                cvt_split_store(sm + SB_H + r*RST + lcg*8,
                                sm + SB_L + r*RST + lcg*8, wv);
            }
        }
        __syncthreads();

        #pragma unroll
        for (int ks = 0; ks < 2; ++ks) {
            uint32_t ah[2][4], al[2][4], bh[2][4], bl[2][4];
            #pragma unroll
            for (int mi = 0; mi < 2; ++mi) {
                ldsm4(ah[mi], sb + SA_H + mi*16*RST + ks*32 + a_lane);
                ldsm4(al[mi], sb + SA_L + mi*16*RST + ks*32 + a_lane);
            }
            #pragma unroll
            for (int j2 = 0; j2 < 2; ++j2) {
                ldsm4(bh[j2], sb + SB_H + j2*16*RST + ks*32 + b_lane);
                ldsm4(bl[j2], sb + SB_L + j2*16*RST + ks*32 + b_lane);
            }
            #pragma unroll
            for (int mi = 0; mi < 2; ++mi)
                #pragma unroll
                for (int j2 = 0; j2 < 2; ++j2)
                    #pragma unroll
                    for (int sub = 0; sub < 2; ++sub) {
                        int ni = j2*2 + sub;
                        mma16816(acc[mi][ni], ah[mi], bh[j2][sub*2], bh[j2][sub*2+1]);
                        mma16816(acc[mi][ni], ah[mi], bl[j2][sub*2], bl[j2][sub*2+1]);
                        mma16816(acc[mi][ni], al[mi], bh[j2][sub*2], bh[j2][sub*2+1]);
                    }
        }
    }

    #pragma unroll
    for (int mi = 0; mi < 2; ++mi) {
        int r = m0 + wr*32 + mi*16 + (lane >> 2);
        #pragma unroll
        for (int ni = 0; ni < 4; ++ni) {
            int ccol = n0 + wc*32 + ni*8 + (lane & 3) * 2;
            float2 bb = *(const float2*)&bias[ccol];
            float2 o0, o1;
            o0.x = acc[mi][ni][0] + bb.x;
            o0.y = acc[mi][ni][1] + bb.y;
            o1.x = acc[mi][ni][2] + bb.x;
            o1.y = acc[mi][ni][3] + bb.y;
            *(float2*)&C[(size_t)r * N + ccol] = o0;
            *(float2*)&C[(size_t)(r + 8) * N + ccol] = o1;
        }
    }
}

// ===========================================================================
// HMMA flash attention, split-bf16 (3-term) on both QK^T and PV.
// Block: 128 queries x (b,h); 8 warps; warp owns 16 query rows end-to-end.
// K row-major [key][d] (non-trans ldmatrix B); V row-major + ldmatrix.trans.
// P stays in registers (C-frag -> A-frag repack). Online softmax per warp.
// ===========================================================================
#define ART 144                       // attention smem row stride (bytes)
#define AQH 0
#define AQL (128*ART)                 // 18432
#define AKH (2*128*ART)               // 36864
#define AKL (AKH + 64*ART)
#define AVH (AKL + 64*ART)
#define AVL (AVH + 64*ART)
#define AMSK (AVL + 64*ART)           // 73728
#define ATTN_SMEM (AMSK + 256)

__global__ __launch_bounds__(256, 2) void attn_hmma(const int* __restrict__ mask)
{
    extern __shared__ char sm[];
    const uint32_t sb = smem_u32(sm);
    float* maskf = (float*)(sm + AMSK);

    const int tid  = threadIdx.x;
    const int lane = tid & 31;
    const int wid  = tid >> 5;
    const int bh   = blockIdx.y;
    const int b    = bh >> 4;
    const int h    = bh & 15;
    const int q0   = blockIdx.x * 128;

    // ---- stage Q (pre-scaled by 1/8, exact) ----
    {
        const int row = tid >> 1;
        const int f0  = (tid & 1) * 8;
        const float* Qg = g_q + (size_t)(b*S_ + q0 + row) * DM + h*DKH;
        #pragma unroll
        for (int u = 0; u < 8; ++u) {
            int f = f0 + u;
            float4 v = *(const float4*)(Qg + f*4);
            v.x *= 0.125f; v.y *= 0.125f; v.z *= 0.125f; v.w *= 0.125f;
            cvt_split_store(sm + AQH + row*ART + f*8, sm + AQL + row*ART + f*8, v);
        }
    }

    // fragment lane addresses
    const uint32_t q_lane = (uint32_t)((wid*16 + (lane & 15)) * ART + (lane >> 4) * 16);
    const uint32_t b_lane = (uint32_t)(((lane & 7) + ((lane >> 4) & 1) * 8) * ART
                                       + ((lane >> 3) & 1) * 16);
    const uint32_t v_lane = (uint32_t)((lane & 15) * ART + (lane >> 4) * 16);

    float o[8][4];
    #pragma unroll
    for (int ni = 0; ni < 8; ni++)
        #pragma unroll
        for (int r = 0; r < 4; r++) o[ni][r] = 0.0f;
    float m0 = -1e30f, m1 = -1e30f, l0 = 0.0f, l1 = 0.0f;

    const int krow = tid >> 2;
    const int kf   = tid & 3;

    for (int t = 0; t < S_/64; ++t) {
        const int k0 = t * 64;
        __syncthreads();   // previous iteration's ldsm consumers done
        // ---- load K, V (64x64 each), mask ----
        {
            const float* Kg = g_k + (size_t)(b*S_ + k0 + krow) * DM + h*DKH;
            const float* Vg = g_v + (size_t)(b*S_ + k0 + krow) * DM + h*DKH;
            #pragma unroll
            for (int u = 0; u < 4; ++u) {
                int f = kf*4 + u;
                float4 kv = *(const float4*)(Kg + f*4);
                cvt_split_store(sm + AKH + krow*ART + f*8, sm + AKL + krow*ART + f*8, kv);
                float4 vv = *(const float4*)(Vg + f*4);
                cvt_split_store(sm + AVH + krow*ART + f*8, sm + AVL + krow*ART + f*8, vv);
            }
            if (tid < 64) maskf[tid] = mask[b*S_ + k0 + tid] ? 0.0f : -1e9f;
        }
        __syncthreads();

        // ---- S = Q K^T (3-term split) ----
        float s[8][4];
        #pragma unroll
        for (int ni = 0; ni < 8; ni++)
            #pragma unroll
            for (int r = 0; r < 4; r++) s[ni][r] = 0.0f;

        #pragma unroll
        for (int kt = 0; kt < 4; ++kt) {
            uint32_t qh[4], ql[4];
            ldsm4(qh, sb + AQH + kt*32 + q_lane);
            ldsm4(ql, sb + AQL + kt*32 + q_lane);
            #pragma unroll
            for (int j2 = 0; j2 < 4; ++j2) {
                uint32_t kh[4], kl[4];
                ldsm4(kh, sb + AKH + j2*16*ART + kt*32 + b_lane);
                ldsm4(kl, sb + AKL + j2*16*ART + kt*32 + b_lane);
                #pragma unroll
                for (int sub = 0; sub < 2; ++sub) {
                    int ni = j2*2 + sub;
                    mma16816(s[ni], qh, kh[sub*2], kh[sub*2+1]);
                    mma16816(s[ni], qh, kl[sub*2], kl[sub*2+1]);
                    mma16816(s[ni], ql, kh[sub*2], kh[sub*2+1]);
                }
            }
        }

        // ---- mask + online softmax (rows r0=lane>>2, r1=r0+8; 4-lane groups) ----
        float mx0 = -1e30f, mx1 = -1e30f;
        #pragma unroll
        for (int ni = 0; ni < 8; ++ni) {
            float2 mv = *(const float2*)&maskf[ni*8 + (lane & 3)*2];
            s[ni][0] += mv.x; s[ni][1] += mv.y;
            s[ni][2] += mv.x; s[ni][3] += mv.y;
            mx0 = fmaxf(mx0, fmaxf(s[ni][0], s[ni][1]));
            mx1 = fmaxf(mx1, fmaxf(s[ni][2], s[ni][3]));
        }
        mx0 = fmaxf(mx0, __shfl_xor_sync(0xffffffffu, mx0, 1));
        mx0 = fmaxf(mx0, __shfl_xor_sync(0xffffffffu, mx0, 2));
        mx1 = fmaxf(mx1, __shfl_xor_sync(0xffffffffu, mx1, 1));
        mx1 = fmaxf(mx1, __shfl_xor_sync(0xffffffffu, mx1, 2));
        float m0n = fmaxf(m0, mx0);
        float m1n = fmaxf(m1, mx1);
        float c0 = __expf(m0 - m0n);
        float c1 = __expf(m1 - m1n);
        float sum0 = 0.0f, sum1 = 0.0f;
        #pragma unroll
        for (int ni = 0; ni < 8; ++ni) {
            s[ni][0] = __expf(s[ni][0] - m0n);
            s[ni][1] = __expf(s[ni][1] - m0n);
            s[ni][2] = __expf(s[ni][2] - m1n);
            s[ni][3] = __expf(s[ni][3] - m1n);
            sum0 += s[ni][0] + s[ni][1];
            sum1 += s[ni][2] + s[ni][3];
        }
        sum0 += __shfl_xor_sync(0xffffffffu, sum0, 1);
        sum0 += __shfl_xor_sync(0xffffffffu, sum0, 2);
        sum1 += __shfl_xor_sync(0xffffffffu, sum1, 1);
        sum1 += __shfl_xor_sync(0xffffffffu, sum1, 2);
        l0 = l0 * c0 + sum0;
        l1 = l1 * c1 + sum1;
        m0 = m0n; m1 = m1n;
        #pragma unroll
        for (int ni = 0; ni < 8; ++ni) {
            o[ni][0] *= c0; o[ni][1] *= c0;
            o[ni][2] *= c1; o[ni][3] *= c1;
        }

        // ---- O += P V (repack P in-register; V frags via ldmatrix.trans) ----
        #pragma unroll
        for (int kt = 0; kt < 4; ++kt) {
            uint32_t pah[4], pal[4];
            pack_split(s[2*kt][0],   s[2*kt][1],   pah[0], pal[0]);
            pack_split(s[2*kt][2],   s[2*kt][3],   pah[1], pal[1]);
            pack_split(s[2*kt+1][0], s[2*kt+1][1], pah[2], pal[2]);
            pack_split(s[2*kt+1][2], s[2*kt+1][3], pah[3], pal[3]);
            #pragma unroll
            for (int jp = 0; jp < 4; ++jp) {
                uint32_t vh[4], vl[4];
                ldsm4t(vh, sb + AVH + kt*16*ART + jp*32 + v_lane);
                ldsm4t(vl, sb + AVL + kt*16*ART + jp*32 + v_lane);
                #pragma unroll
                for (int sub = 0; sub < 2; ++sub) {
                    int ni = jp*2 + sub;
                    mma16816(o[ni], pah, vh[sub*2], vh[sub*2+1]);
                    mma16816(o[ni], pah, vl[sub*2], vl[sub*2+1]);
                    mma16816(o[ni], pal, vh[sub*2], vh[sub*2+1]);
                }
            }
        }
    }

    // ---- epilogue: normalize, store to g_c[b, q, h*64+d] ----
    const float inv0 = 1.0f / l0;
    const float inv1 = 1.0f / l1;
    const int r0 = q0 + wid*16 + (lane >> 2);
    #pragma unroll
    for (int ni = 0; ni < 8; ++ni) {
        int col = h*DKH + ni*8 + (lane & 3)*2;
        float2 w0, w1;
        w0.x = o[ni][0] * inv0; w0.y = o[ni][1] * inv0;
        w1.x = o[ni][2] * inv1; w1.y = o[ni][3] * inv1;
        *(float2*)&g_c[(size_t)(b*S_ + r0) * DM + col] = w0;
        *(float2*)&g_c[(size_t)(b*S_ + r0 + 8) * DM + col] = w1;
    }
}

// ---------------------------------------------------------------------------
extern "C" void kernel_launch(void* const* d_in, const int* in_sizes, int n_in,
                              void* d_out, int out_size)
{
    const float* q    = (const float*)d_in[0];
    const float* k    = (const float*)d_in[1];
    const float* v    = (const float*)d_in[2];
    const int*   mask = (const int*)  d_in[3];
    const float* Wq   = (const float*)d_in[4];
    const float* bq   = (const float*)d_in[5];
    const float* Wk   = (const float*)d_in[6];
    const float* bk   = (const float*)d_in[7];
    const float* Wv   = (const float*)d_in[8];
    const float* bv   = (const float*)d_in[9];
    const float* Wo   = (const float*)d_in[10];
    const float* bo   = (const float*)d_in[11];
    float* out = (float*)d_out;

    float *pq, *pk, *pv, *pc;
    cudaGetSymbolAddress((void**)&pq, g_q);
    cudaGetSymbolAddress((void**)&pk, g_k);
    cudaGetSymbolAddress((void**)&pv, g_v);
    cudaGetSymbolAddress((void**)&pc, g_c);

    cudaFuncSetAttribute(attn_hmma, cudaFuncAttributeMaxDynamicSharedMemorySize, ATTN_SMEM);

    const dim3 gg(DM/64, MR/128);   // (16, 32)
    gemm_hmma<<<gg, 256>>>(q, Wq, bq, pq, MR, DM, DM);
    gemm_hmma<<<gg, 256>>>(k, Wk, bk, pk, MR, DM, DM);
    gemm_hmma<<<gg, 256>>>(v, Wv, bv, pv, MR, DM, DM);

    attn_hmma<<<dim3(S_/128, B_*NH), 256, ATTN_SMEM>>>(mask);

    gemm_hmma<<<gg, 256>>>(pc, Wo, bo, out, MR, DM, DM);
}

// round 10
// speedup vs baseline: 2.7553x; 1.1911x over previous
#include <cuda_runtime.h>
#include <cuda_bf16.h>
#include <cstdint>

#define DM 1024
#define NH 16
#define DKH 64
#define B_ 2
#define S_ 2048
#define MR (B_*S_)   // 4096 rows

typedef __nv_bfloat16 bf16;

// ---- persistent split-bf16 scratch (allocation-free rule: device globals) ----
__device__ bf16 g_qh[MR*DM], g_ql[MR*DM], g_kh[MR*DM], g_kl[MR*DM], g_vh[MR*DM], g_vl[MR*DM];
__device__ bf16 g_wqh[DM*DM], g_wql[DM*DM], g_wkh[DM*DM], g_wkl[DM*DM];
__device__ bf16 g_wvh[DM*DM], g_wvl[DM*DM], g_woh[DM*DM], g_wol[DM*DM];
__device__ bf16 g_pqh[MR*DM], g_pql[MR*DM], g_pkh[MR*DM], g_pkl[MR*DM], g_pvh[MR*DM], g_pvl[MR*DM];
__device__ bf16 g_ch[MR*DM], g_cl[MR*DM];

// ===========================================================================
// Helpers
// ===========================================================================
__device__ __forceinline__ uint32_t smem_u32(const void* p) {
    uint32_t a;
    asm("{ .reg .u64 t; cvta.to.shared.u64 t, %1; cvt.u32.u64 %0, t; }" : "=r"(a) : "l"(p));
    return a;
}
__device__ __forceinline__ void ldsm4(uint32_t r[4], uint32_t addr) {
    asm volatile("ldmatrix.sync.aligned.m8n8.x4.shared.b16 {%0,%1,%2,%3}, [%4];"
                 : "=r"(r[0]), "=r"(r[1]), "=r"(r[2]), "=r"(r[3]) : "r"(addr));
}
__device__ __forceinline__ void ldsm4t(uint32_t r[4], uint32_t addr) {
    asm volatile("ldmatrix.sync.aligned.m8n8.x4.trans.shared.b16 {%0,%1,%2,%3}, [%4];"
                 : "=r"(r[0]), "=r"(r[1]), "=r"(r[2]), "=r"(r[3]) : "r"(addr));
}
__device__ __forceinline__ void mma16816(float c[4], const uint32_t a[4],
                                         uint32_t b0, uint32_t b1) {
    asm volatile(
        "mma.sync.aligned.m16n8k16.row.col.f32.bf16.bf16.f32 "
        "{%0,%1,%2,%3}, {%4,%5,%6,%7}, {%8,%9}, {%0,%1,%2,%3};"
        : "+f"(c[0]), "+f"(c[1]), "+f"(c[2]), "+f"(c[3])
        : "r"(a[0]), "r"(a[1]), "r"(a[2]), "r"(a[3]), "r"(b0), "r"(b1));
}
__device__ __forceinline__ void cp16(uint32_t s, const void* g) {
    asm volatile("cp.async.cg.shared.global [%0], [%1], 16;" :: "r"(s), "l"(g));
}
#define CP_COMMIT() asm volatile("cp.async.commit_group;" ::: "memory")
#define CP_WAIT0()  asm volatile("cp.async.wait_group 0;" ::: "memory")
#define CP_WAIT1()  asm volatile("cp.async.wait_group 1;" ::: "memory")

// Split fp32x4 -> 4 bf16 hi + 4 bf16 lo (8 bytes each)
__device__ __forceinline__ void cvt_split_store(void* hi, void* lo, float4 v) {
    __nv_bfloat16 h0 = __float2bfloat16_rn(v.x);
    __nv_bfloat16 h1 = __float2bfloat16_rn(v.y);
    __nv_bfloat16 h2 = __float2bfloat16_rn(v.z);
    __nv_bfloat16 h3 = __float2bfloat16_rn(v.w);
    float l0 = v.x - __bfloat162float(h0);
    float l1 = v.y - __bfloat162float(h1);
    float l2 = v.z - __bfloat162float(h2);
    float l3 = v.w - __bfloat162float(h3);
    union { __nv_bfloat162 b[2]; uint2 u; } H, L;
    H.b[0] = __halves2bfloat162(h0, h1);
    H.b[1] = __halves2bfloat162(h2, h3);
    L.b[0] = __halves2bfloat162(__float2bfloat16_rn(l0), __float2bfloat16_rn(l1));
    L.b[1] = __halves2bfloat162(__float2bfloat16_rn(l2), __float2bfloat16_rn(l3));
    *(uint2*)hi = H.u;
    *(uint2*)lo = L.u;
}
__device__ __forceinline__ void pack_split(float e, float o2, uint32_t& hi, uint32_t& lo) {
    __nv_bfloat162 H = __floats2bfloat162_rn(e, o2);
    float re = e - __low2float(H);
    float ro = o2 - __high2float(H);
    __nv_bfloat162 L = __floats2bfloat162_rn(re, ro);
    hi = reinterpret_cast<uint32_t&>(H);
    lo = reinterpret_cast<uint32_t&>(L);
}

// ===========================================================================
// prep: fp32 -> split bf16 hi/lo
// ===========================================================================
__global__ __launch_bounds__(256) void prep_split(
    const float* __restrict__ in, bf16* __restrict__ hi, bf16* __restrict__ lo, int n4)
{
    int i = blockIdx.x * blockDim.x + threadIdx.x;
    if (i < n4) {
        float4 v = ((const float4*)in)[i];
        cvt_split_store((uint2*)hi + i, (uint2*)lo + i, v);
    }
}

// ===========================================================================
// Double-buffered split-bf16 HMMA GEMM:  C = A @ W^T + bias
// A given as Ah/Al [M,K] bf16; W as Wh/Wl [N,K] bf16.  Block 128x64, BK=32.
// 3 MMAs per frag: Ah*Bh + Ah*Bl + Al*Bh.  Optional split-bf16 output.
// ===========================================================================
#define RST 80
#define SA_H 0
#define SA_L (128*RST)                // 10240
#define SB_H (2*128*RST)              // 20480
#define SB_L (SB_H + 64*RST)          // 25600
#define STG  (SB_L + 64*RST)          // 30720 per stage
#define GEMM_SMEM (2*STG)             // 61440

__device__ __forceinline__ void gemm_load_chunk(
    uint32_t s0, int r, int sg, size_t go, size_t aRowHalf,
    const char* gAh, const char* gAl, const char* gWh, const char* gWl)
{
    cp16(s0 + SA_H + r*RST + sg,        gAh + go);
    cp16(s0 + SA_H + (r+64)*RST + sg,   gAh + aRowHalf + go);
    cp16(s0 + SA_L + r*RST + sg,        gAl + go);
    cp16(s0 + SA_L + (r+64)*RST + sg,   gAl + aRowHalf + go);
    cp16(s0 + SB_H + r*RST + sg,        gWh + go);
    cp16(s0 + SB_L + r*RST + sg,        gWl + go);
}

__global__ __launch_bounds__(256, 2) void gemm_bf3(
    const bf16* __restrict__ Ah, const bf16* __restrict__ Al,
    const bf16* __restrict__ Wh, const bf16* __restrict__ Wl,
    const float* __restrict__ bias,
    float* __restrict__ C, bf16* __restrict__ Ch, bf16* __restrict__ Cl,
    int M, int N, int K, int split_out)
{
    extern __shared__ char sm[];
    const uint32_t sb = smem_u32(sm);

    const int tid  = threadIdx.x;
    const int lane = tid & 31;
    const int wid  = tid >> 5;
    const int wr   = wid >> 1;
    const int wc   = wid & 1;
    const int m0   = blockIdx.y * 128;
    const int n0   = blockIdx.x * 64;

    // loader mapping: r = row 0..63, sg = 16B segment within 64B row-chunk
    const int r  = tid >> 2;
    const int sg = (tid & 3) * 16;
    const char* gAh = (const char*)(Ah + (size_t)(m0 + r) * K) + sg;
    const char* gAl = (const char*)(Al + (size_t)(m0 + r) * K) + sg;
    const char* gWh = (const char*)(Wh + (size_t)(n0 + r) * K) + sg;
    const char* gWl = (const char*)(Wl + (size_t)(n0 + r) * K) + sg;
    const size_t aRowHalf = (size_t)64 * K * 2;

    const uint32_t a_lane = (uint32_t)((wr*32 + (lane & 15)) * RST + (lane >> 4) * 16);
    const uint32_t b_lane = (uint32_t)((wc*32 + (lane & 7) + ((lane >> 4) & 1) * 8) * RST
                                       + ((lane >> 3) & 1) * 16);

    float acc[2][4][4];
    #pragma unroll
    for (int mi = 0; mi < 2; mi++)
        #pragma unroll
        for (int ni = 0; ni < 4; ni++)
            #pragma unroll
            for (int rr = 0; rr < 4; rr++) acc[mi][ni][rr] = 0.0f;

    const int NCH = K / 32;   // 32 chunks, each 32 bf16 = 64 bytes
    gemm_load_chunk(sb, r, sg, 0, aRowHalf, gAh, gAl, gWh, gWl);
    CP_COMMIT();

    for (int ch = 0; ch < NCH; ++ch) {
        const uint32_t s0 = sb + (uint32_t)(ch & 1) * STG;
        if (ch + 1 < NCH) {
            gemm_load_chunk(sb + (uint32_t)((ch + 1) & 1) * STG, r, sg,
                            (size_t)(ch + 1) * 64, aRowHalf, gAh, gAl, gWh, gWl);
            CP_COMMIT();
            CP_WAIT1();
        } else {
            CP_WAIT0();
        }
        __syncthreads();

        #pragma unroll
        for (int ks = 0; ks < 2; ++ks) {
            uint32_t ah[2][4], al[2][4], bh[2][4], bl[2][4];
            #pragma unroll
            for (int mi = 0; mi < 2; ++mi) {
                ldsm4(ah[mi], s0 + SA_H + mi*16*RST + ks*32 + a_lane);
                ldsm4(al[mi], s0 + SA_L + mi*16*RST + ks*32 + a_lane);
            }
            #pragma unroll
            for (int j2 = 0; j2 < 2; ++j2) {
                ldsm4(bh[j2], s0 + SB_H + j2*16*RST + ks*32 + b_lane);
                ldsm4(bl[j2], s0 + SB_L + j2*16*RST + ks*32 + b_lane);
            }
            #pragma unroll
            for (int mi = 0; mi < 2; ++mi)
                #pragma unroll
                for (int j2 = 0; j2 < 2; ++j2)
                    #pragma unroll
                    for (int sub = 0; sub < 2; ++sub) {
                        int ni = j2*2 + sub;
                        mma16816(acc[mi][ni], ah[mi], bh[j2][sub*2], bh[j2][sub*2+1]);
                        mma16816(acc[mi][ni], ah[mi], bl[j2][sub*2], bl[j2][sub*2+1]);
                        mma16816(acc[mi][ni], al[mi], bh[j2][sub*2], bh[j2][sub*2+1]);
                    }
        }
        __syncthreads();
    }

    // ---- epilogue ----
    #pragma unroll
    for (int mi = 0; mi < 2; ++mi) {
        int rr = m0 + wr*32 + mi*16 + (lane >> 2);
        #pragma unroll
        for (int ni = 0; ni < 4; ++ni) {
            int ccol = n0 + wc*32 + ni*8 + (lane & 3) * 2;
            float2 bb = *(const float2*)&bias[ccol];
            float2 o0, o1;
            o0.x = acc[mi][ni][0] + bb.x;
            o0.y = acc[mi][ni][1] + bb.y;
            o1.x = acc[mi][ni][2] + bb.x;
            o1.y = acc[mi][ni][3] + bb.y;
            if (split_out) {
                uint32_t hi, lo;
                pack_split(o0.x, o0.y, hi, lo);
                *(uint32_t*)&Ch[(size_t)rr * N + ccol] = hi;
                *(uint32_t*)&Cl[(size_t)rr * N + ccol] = lo;
                pack_split(o1.x, o1.y, hi, lo);
                *(uint32_t*)&Ch[(size_t)(rr + 8) * N + ccol] = hi;
                *(uint32_t*)&Cl[(size_t)(rr + 8) * N + ccol] = lo;
            } else {
                *(float2*)&C[(size_t)rr * N + ccol] = o0;
                *(float2*)&C[(size_t)(rr + 8) * N + ccol] = o1;
            }
        }
    }
}

// ===========================================================================
// HMMA flash attention, split-bf16 inputs pre-staged in globals.
// Block: 128 queries x (b,h); 8 warps; warp owns 16 query rows.
// Scale 1/8 applied post-MMA (exact). Ctx written split bf16 for final GEMM.
// ===========================================================================
#define ART 144
#define AQH 0
#define AQL (128*ART)                 // 18432
#define AKH (2*128*ART)               // 36864
#define AKL (AKH + 64*ART)
#define AVH (AKL + 64*ART)
#define AVL (AVH + 64*ART)
#define AMSK (AVL + 64*ART)           // 73728
#define ATTN_SMEM (AMSK + 256)

__global__ __launch_bounds__(256, 2) void attn_hmma(const int* __restrict__ mask)
{
    extern __shared__ char sm[];
    const uint32_t sb = smem_u32(sm);
    float* maskf = (float*)(sm + AMSK);

    const int tid  = threadIdx.x;
    const int lane = tid & 31;
    const int wid  = tid >> 5;
    const int bh   = blockIdx.y;
    const int b    = bh >> 4;
    const int h    = bh & 15;
    const int q0   = blockIdx.x * 128;

    // ---- stage Q (bf16 hi/lo, plain copies) ----
    {
        const int row = tid >> 1;
        const int hf  = (tid & 1) * 4;
        const size_t qb = (size_t)(b*S_ + q0 + row) * DM + h*DKH;
        #pragma unroll
        for (int u = 0; u < 4; ++u) {
            int idx = hf + u;
            *(uint4*)(sm + AQH + row*ART + idx*16) = *(const uint4*)(g_pqh + qb + idx*8);
            *(uint4*)(sm + AQL + row*ART + idx*16) = *(const uint4*)(g_pql + qb + idx*8);
        }
    }

    const uint32_t q_lane = (uint32_t)((wid*16 + (lane & 15)) * ART + (lane >> 4) * 16);
    const uint32_t b_lane = (uint32_t)(((lane & 7) + ((lane >> 4) & 1) * 8) * ART
                                       + ((lane >> 3) & 1) * 16);
    const uint32_t v_lane = (uint32_t)((lane & 15) * ART + (lane >> 4) * 16);

    float o[8][4];
    #pragma unroll
    for (int ni = 0; ni < 8; ni++)
        #pragma unroll
        for (int rr = 0; rr < 4; rr++) o[ni][rr] = 0.0f;
    float m0 = -1e30f, m1 = -1e30f, l0 = 0.0f, l1 = 0.0f;

    const int krow = tid >> 2;
    const int ksg  = tid & 3;

    for (int t = 0; t < S_/64; ++t) {
        const int k0 = t * 64;
        __syncthreads();
        // ---- load K, V tiles (bf16 hi/lo) + mask ----
        {
            const size_t base = (size_t)(b*S_ + k0 + krow) * DM + h*DKH;
            #pragma unroll
            for (int u = 0; u < 2; ++u) {
                int idx = ksg*2 + u;
                *(uint4*)(sm + AKH + krow*ART + idx*16) = *(const uint4*)(g_pkh + base + idx*8);
                *(uint4*)(sm + AKL + krow*ART + idx*16) = *(const uint4*)(g_pkl + base + idx*8);
                *(uint4*)(sm + AVH + krow*ART + idx*16) = *(const uint4*)(g_pvh + base + idx*8);
                *(uint4*)(sm + AVL + krow*ART + idx*16) = *(const uint4*)(g_pvl + base + idx*8);
            }
            if (tid < 64) maskf[tid] = mask[b*S_ + k0 + tid] ? 0.0f : -1e9f;
        }
        __syncthreads();

        // ---- S = Q K^T (3-term split) ----
        float s[8][4];
        #pragma unroll
        for (int ni = 0; ni < 8; ni++)
            #pragma unroll
            for (int rr = 0; rr < 4; rr++) s[ni][rr] = 0.0f;

        #pragma unroll
        for (int kt = 0; kt < 4; ++kt) {
            uint32_t qh[4], ql[4];
            ldsm4(qh, sb + AQH + kt*32 + q_lane);
            ldsm4(ql, sb + AQL + kt*32 + q_lane);
            #pragma unroll
            for (int j2 = 0; j2 < 4; ++j2) {
                uint32_t kh[4], kl[4];
                ldsm4(kh, sb + AKH + j2*16*ART + kt*32 + b_lane);
                ldsm4(kl, sb + AKL + j2*16*ART + kt*32 + b_lane);
                #pragma unroll
                for (int sub = 0; sub < 2; ++sub) {
                    int ni = j2*2 + sub;
                    mma16816(s[ni], qh, kh[sub*2], kh[sub*2+1]);
                    mma16816(s[ni], qh, kl[sub*2], kl[sub*2+1]);
                    mma16816(s[ni], ql, kh[sub*2], kh[sub*2+1]);
                }
            }
        }

        // ---- scale + mask + online softmax ----
        float mx0 = -1e30f, mx1 = -1e30f;
        #pragma unroll
        for (int ni = 0; ni < 8; ++ni) {
            float2 mv = *(const float2*)&maskf[ni*8 + (lane & 3)*2];
            s[ni][0] = fmaf(s[ni][0], 0.125f, mv.x);
            s[ni][1] = fmaf(s[ni][1], 0.125f, mv.y);
            s[ni][2] = fmaf(s[ni][2], 0.125f, mv.x);
            s[ni][3] = fmaf(s[ni][3], 0.125f, mv.y);
            mx0 = fmaxf(mx0, fmaxf(s[ni][0], s[ni][1]));
            mx1 = fmaxf(mx1, fmaxf(s[ni][2], s[ni][3]));
        }
        mx0 = fmaxf(mx0, __shfl_xor_sync(0xffffffffu, mx0, 1));
        mx0 = fmaxf(mx0, __shfl_xor_sync(0xffffffffu, mx0, 2));
        mx1 = fmaxf(mx1, __shfl_xor_sync(0xffffffffu, mx1, 1));
        mx1 = fmaxf(mx1, __shfl_xor_sync(0xffffffffu, mx1, 2));
        float m0n = fmaxf(m0, mx0);
        float m1n = fmaxf(m1, mx1);
        float c0 = __expf(m0 - m0n);
        float c1 = __expf(m1 - m1n);
        float sum0 = 0.0f, sum1 = 0.0f;
        #pragma unroll
        for (int ni = 0; ni < 8; ++ni) {
            s[ni][0] = __expf(s[ni][0] - m0n);
            s[ni][1] = __expf(s[ni][1] - m0n);
            s[ni][2] = __expf(s[ni][2] - m1n);
            s[ni][3] = __expf(s[ni][3] - m1n);
            sum0 += s[ni][0] + s[ni][1];
            sum1 += s[ni][2] + s[ni][3];
        }
        sum0 += __shfl_xor_sync(0xffffffffu, sum0, 1);
        sum0 += __shfl_xor_sync(0xffffffffu, sum0, 2);
        sum1 += __shfl_xor_sync(0xffffffffu, sum1, 1);
        sum1 += __shfl_xor_sync(0xffffffffu, sum1, 2);
        l0 = l0 * c0 + sum0;
        l1 = l1 * c1 + sum1;
        m0 = m0n; m1 = m1n;
        #pragma unroll
        for (int ni = 0; ni < 8; ++ni) {
            o[ni][0] *= c0; o[ni][1] *= c0;
            o[ni][2] *= c1; o[ni][3] *= c1;
        }

        // ---- O += P V ----
        #pragma unroll
        for (int kt = 0; kt < 4; ++kt) {
            uint32_t pah[4], pal[4];
            pack_split(s[2*kt][0],   s[2*kt][1],   pah[0], pal[0]);
            pack_split(s[2*kt][2],   s[2*kt][3],   pah[1], pal[1]);
            pack_split(s[2*kt+1][0], s[2*kt+1][1], pah[2], pal[2]);
            pack_split(s[2*kt+1][2], s[2*kt+1][3], pah[3], pal[3]);
            #pragma unroll
            for (int jp = 0; jp < 4; ++jp) {
                uint32_t vh[4], vl[4];
                ldsm4t(vh, sb + AVH + kt*16*ART + jp*32 + v_lane);
                ldsm4t(vl, sb + AVL + kt*16*ART + jp*32 + v_lane);
                #pragma unroll
                for (int sub = 0; sub < 2; ++sub) {
                    int ni = jp*2 + sub;
                    mma16816(o[ni], pah, vh[sub*2], vh[sub*2+1]);
                    mma16816(o[ni], pah, vl[sub*2], vl[sub*2+1]);
                    mma16816(o[ni], pal, vh[sub*2], vh[sub*2+1]);
                }
            }
        }
    }

    // ---- epilogue: normalize, write ctx split-bf16 ----
    const float inv0 = 1.0f / l0;
    const float inv1 = 1.0f / l1;
    const int r0 = q0 + wid*16 + (lane >> 2);
    #pragma unroll
    for (int ni = 0; ni < 8; ++ni) {
        int col = h*DKH + ni*8 + (lane & 3)*2;
        uint32_t hi, lo;
        size_t e0 = (size_t)(b*S_ + r0) * DM + col;
        size_t e1 = (size_t)(b*S_ + r0 + 8) * DM + col;
        pack_split(o[ni][0] * inv0, o[ni][1] * inv0, hi, lo);
        *(uint32_t*)&g_ch[e0] = hi;
        *(uint32_t*)&g_cl[e0] = lo;
        pack_split(o[ni][2] * inv1, o[ni][3] * inv1, hi, lo);
        *(uint32_t*)&g_ch[e1] = hi;
        *(uint32_t*)&g_cl[e1] = lo;
    }
}

// ---------------------------------------------------------------------------
extern "C" void kernel_launch(void* const* d_in, const int* in_sizes, int n_in,
                              void* d_out, int out_size)
{
    const float* q    = (const float*)d_in[0];
    const float* k    = (const float*)d_in[1];
    const float* v    = (const float*)d_in[2];
    const int*   mask = (const int*)  d_in[3];
    const float* Wq   = (const float*)d_in[4];
    const float* bq   = (const float*)d_in[5];
    const float* Wk   = (const float*)d_in[6];
    const float* bk   = (const float*)d_in[7];
    const float* Wv   = (const float*)d_in[8];
    const float* bv   = (const float*)d_in[9];
    const float* Wo   = (const float*)d_in[10];
    const float* bo   = (const float*)d_in[11];
    float* out = (float*)d_out;

    bf16 *qh, *ql, *kh, *kl, *vh, *vl;
    bf16 *wqh, *wql, *wkh, *wkl, *wvh, *wvl, *woh, *wol;
    bf16 *pqh, *pql, *pkh, *pkl, *pvh, *pvl, *ch, *cl;
    cudaGetSymbolAddress((void**)&qh, g_qh);   cudaGetSymbolAddress((void**)&ql, g_ql);
    cudaGetSymbolAddress((void**)&kh, g_kh);   cudaGetSymbolAddress((void**)&kl, g_kl);
    cudaGetSymbolAddress((void**)&vh, g_vh);   cudaGetSymbolAddress((void**)&vl, g_vl);
    cudaGetSymbolAddress((void**)&wqh, g_wqh); cudaGetSymbolAddress((void**)&wql, g_wql);
    cudaGetSymbolAddress((void**)&wkh, g_wkh); cudaGetSymbolAddress((void**)&wkl, g_wkl);
    cudaGetSymbolAddress((void**)&wvh, g_wvh); cudaGetSymbolAddress((void**)&wvl, g_wvl);
    cudaGetSymbolAddress((void**)&woh, g_woh); cudaGetSymbolAddress((void**)&wol, g_wol);
    cudaGetSymbolAddress((void**)&pqh, g_pqh); cudaGetSymbolAddress((void**)&pql, g_pql);
    cudaGetSymbolAddress((void**)&pkh, g_pkh); cudaGetSymbolAddress((void**)&pkl, g_pkl);
    cudaGetSymbolAddress((void**)&pvh, g_pvh); cudaGetSymbolAddress((void**)&pvl, g_pvl);
    cudaGetSymbolAddress((void**)&ch, g_ch);   cudaGetSymbolAddress((void**)&cl, g_cl);

    cudaFuncSetAttribute(gemm_bf3, cudaFuncAttributeMaxDynamicSharedMemorySize, GEMM_SMEM);
    cudaFuncSetAttribute(attn_hmma, cudaFuncAttributeMaxDynamicSharedMemorySize, ATTN_SMEM);

    // 1) prep: split inputs + weights
    const int NI4 = MR*DM/4, NW4 = DM*DM/4;
    prep_split<<<NI4/256, 256>>>(q,  qh,  ql,  NI4);
    prep_split<<<NI4/256, 256>>>(k,  kh,  kl,  NI4);
    prep_split<<<NI4/256, 256>>>(v,  vh,  vl,  NI4);
    prep_split<<<NW4/256, 256>>>(Wq, wqh, wql, NW4);
    prep_split<<<NW4/256, 256>>>(Wk, wkh, wkl, NW4);
    prep_split<<<NW4/256, 256>>>(Wv, wvh, wvl, NW4);
    prep_split<<<NW4/256, 256>>>(Wo, woh, wol, NW4);

    // 2) projections (split-bf16 output)
    const dim3 gg(DM/64, MR/128);   // (16, 32)
    gemm_bf3<<<gg, 256, GEMM_SMEM>>>(qh, ql, wqh, wql, bq, nullptr, pqh, pql, MR, DM, DM, 1);
    gemm_bf3<<<gg, 256, GEMM_SMEM>>>(kh, kl, wkh, wkl, bk, nullptr, pkh, pkl, MR, DM, DM, 1);
    gemm_bf3<<<gg, 256, GEMM_SMEM>>>(vh, vl, wvh, wvl, bv, nullptr, pvh, pvl, MR, DM, DM, 1);

    // 3) attention (reads split proj, writes split ctx)
    attn_hmma<<<dim3(S_/128, B_*NH), 256, ATTN_SMEM>>>(mask);

    // 4) output projection (fp32 out)
    gemm_bf3<<<gg, 256, GEMM_SMEM>>>(ch, cl, woh, wol, bo, out, nullptr, nullptr, MR, DM, DM, 0);
}

// round 11
// speedup vs baseline: 2.8393x; 1.0305x over previous
#include <cuda_runtime.h>
#include <cuda_bf16.h>
#include <cstdint>

#define DM 1024
#define NH 16
#define DKH 64
#define B_ 2
#define S_ 2048
#define MR (B_*S_)   // 4096 rows

typedef __nv_bfloat16 bf16;

// ---- persistent split-bf16 scratch (allocation-free rule: device globals) ----
__device__ bf16 g_qh[MR*DM], g_ql[MR*DM], g_kh[MR*DM], g_kl[MR*DM], g_vh[MR*DM], g_vl[MR*DM];
__device__ bf16 g_wqh[DM*DM], g_wql[DM*DM], g_wkh[DM*DM], g_wkl[DM*DM];
__device__ bf16 g_wvh[DM*DM], g_wvl[DM*DM], g_woh[DM*DM], g_wol[DM*DM];
__device__ bf16 g_pqh[MR*DM], g_pql[MR*DM], g_pkh[MR*DM], g_pkl[MR*DM], g_pvh[MR*DM], g_pvl[MR*DM];
__device__ bf16 g_ch[MR*DM], g_cl[MR*DM];

// ===========================================================================
// Helpers
// ===========================================================================
__device__ __forceinline__ uint32_t smem_u32(const void* p) {
    uint32_t a;
    asm("{ .reg .u64 t; cvta.to.shared.u64 t, %1; cvt.u32.u64 %0, t; }" : "=r"(a) : "l"(p));
    return a;
}
__device__ __forceinline__ void ldsm4(uint32_t r[4], uint32_t addr) {
    asm volatile("ldmatrix.sync.aligned.m8n8.x4.shared.b16 {%0,%1,%2,%3}, [%4];"
                 : "=r"(r[0]), "=r"(r[1]), "=r"(r[2]), "=r"(r[3]) : "r"(addr));
}
__device__ __forceinline__ void ldsm4t(uint32_t r[4], uint32_t addr) {
    asm volatile("ldmatrix.sync.aligned.m8n8.x4.trans.shared.b16 {%0,%1,%2,%3}, [%4];"
                 : "=r"(r[0]), "=r"(r[1]), "=r"(r[2]), "=r"(r[3]) : "r"(addr));
}
__device__ __forceinline__ void mma16816(float c[4], const uint32_t a[4],
                                         uint32_t b0, uint32_t b1) {
    asm volatile(
        "mma.sync.aligned.m16n8k16.row.col.f32.bf16.bf16.f32 "
        "{%0,%1,%2,%3}, {%4,%5,%6,%7}, {%8,%9}, {%0,%1,%2,%3};"
        : "+f"(c[0]), "+f"(c[1]), "+f"(c[2]), "+f"(c[3])
        : "r"(a[0]), "r"(a[1]), "r"(a[2]), "r"(a[3]), "r"(b0), "r"(b1));
}
__device__ __forceinline__ void cp16(uint32_t s, const void* g) {
    asm volatile("cp.async.cg.shared.global [%0], [%1], 16;" :: "r"(s), "l"(g));
}
#define CP_COMMIT() asm volatile("cp.async.commit_group;" ::: "memory")
#define CP_WAIT0()  asm volatile("cp.async.wait_group 0;" ::: "memory")
#define CP_WAIT1()  asm volatile("cp.async.wait_group 1;" ::: "memory")
#define CP_WAIT2()  asm volatile("cp.async.wait_group 2;" ::: "memory")

__device__ __forceinline__ void cvt_split_store(void* hi, void* lo, float4 v) {
    __nv_bfloat16 h0 = __float2bfloat16_rn(v.x);
    __nv_bfloat16 h1 = __float2bfloat16_rn(v.y);
    __nv_bfloat16 h2 = __float2bfloat16_rn(v.z);
    __nv_bfloat16 h3 = __float2bfloat16_rn(v.w);
    float l0 = v.x - __bfloat162float(h0);
    float l1 = v.y - __bfloat162float(h1);
    float l2 = v.z - __bfloat162float(h2);
    float l3 = v.w - __bfloat162float(h3);
    union { __nv_bfloat162 b[2]; uint2 u; } H, L;
    H.b[0] = __halves2bfloat162(h0, h1);
    H.b[1] = __halves2bfloat162(h2, h3);
    L.b[0] = __halves2bfloat162(__float2bfloat16_rn(l0), __float2bfloat16_rn(l1));
    L.b[1] = __halves2bfloat162(__float2bfloat16_rn(l2), __float2bfloat16_rn(l3));
    *(uint2*)hi = H.u;
    *(uint2*)lo = L.u;
}
__device__ __forceinline__ void pack_split(float e, float o2, uint32_t& hi, uint32_t& lo) {
    __nv_bfloat162 H = __floats2bfloat162_rn(e, o2);
    float re = e - __low2float(H);
    float ro = o2 - __high2float(H);
    __nv_bfloat162 L = __floats2bfloat162_rn(re, ro);
    hi = reinterpret_cast<uint32_t&>(H);
    lo = reinterpret_cast<uint32_t&>(L);
}

// ===========================================================================
// prep: fp32 -> split bf16 hi/lo (batched over up to 4 tensors via blockIdx.y)
// ===========================================================================
struct PrepArgs {
    const float* in[4];
    bf16* hi[4];
    bf16* lo[4];
};
__global__ __launch_bounds__(256) void prep_split_n(PrepArgs p, int n4)
{
    int i = blockIdx.x * blockDim.x + threadIdx.x;
    int s = blockIdx.y;
    if (i < n4) {
        float4 v = ((const float4*)p.in[s])[i];
        cvt_split_store((uint2*)p.hi[s] + i, (uint2*)p.lo[s] + i, v);
    }
}

// ===========================================================================
// 3-stage cp.async split-bf16 HMMA GEMM core.  Block 128x64, BK=32.
// ===========================================================================
#define RST 80
#define SA_H 0
#define SA_L (128*RST)                // 10240
#define SB_H (2*128*RST)              // 20480
#define SB_L (SB_H + 64*RST)          // 25600
#define STG  (SB_L + 64*RST)          // 30720 per stage
#define GEMM_SMEM (3*STG)             // 92160

__device__ __forceinline__ void gemm_load_chunk(
    uint32_t s0, int r, int sg, size_t go, size_t aRowHalf,
    const char* gAh, const char* gAl, const char* gWh, const char* gWl)
{
    cp16(s0 + SA_H + r*RST + sg,        gAh + go);
    cp16(s0 + SA_H + (r+64)*RST + sg,   gAh + aRowHalf + go);
    cp16(s0 + SA_L + r*RST + sg,        gAl + go);
    cp16(s0 + SA_L + (r+64)*RST + sg,   gAl + aRowHalf + go);
    cp16(s0 + SB_H + r*RST + sg,        gWh + go);
    cp16(s0 + SB_L + r*RST + sg,        gWl + go);
}

// Shared mainloop: accumulates into acc.  Returns after last chunk.
__device__ __forceinline__ void gemm_mainloop(
    uint32_t sb, int r, int sg, size_t aRowHalf,
    const char* gAh, const char* gAl, const char* gWh, const char* gWl,
    uint32_t a_lane, uint32_t b_lane, float acc[2][4][4], int K)
{
    const int NCH = K / 32;
    gemm_load_chunk(sb + 0*STG, r, sg, 0,  aRowHalf, gAh, gAl, gWh, gWl);
    CP_COMMIT();
    gemm_load_chunk(sb + 1*STG, r, sg, 64, aRowHalf, gAh, gAl, gWh, gWl);
    CP_COMMIT();

    for (int ch = 0; ch < NCH; ++ch) {
        const uint32_t s0 = sb + (uint32_t)(ch % 3) * STG;
        if (ch + 2 < NCH) {
            gemm_load_chunk(sb + (uint32_t)((ch + 2) % 3) * STG, r, sg,
                            (size_t)(ch + 2) * 64, aRowHalf, gAh, gAl, gWh, gWl);
            CP_COMMIT();
            CP_WAIT2();
        } else if (ch + 1 < NCH) {
            CP_WAIT1();
        } else {
            CP_WAIT0();
        }
        __syncthreads();

        #pragma unroll
        for (int ks = 0; ks < 2; ++ks) {
            uint32_t ah[2][4], al[2][4], bh[2][4], bl[2][4];
            #pragma unroll
            for (int mi = 0; mi < 2; ++mi) {
                ldsm4(ah[mi], s0 + SA_H + mi*16*RST + ks*32 + a_lane);
                ldsm4(al[mi], s0 + SA_L + mi*16*RST + ks*32 + a_lane);
            }
            #pragma unroll
            for (int j2 = 0; j2 < 2; ++j2) {
                ldsm4(bh[j2], s0 + SB_H + j2*16*RST + ks*32 + b_lane);
                ldsm4(bl[j2], s0 + SB_L + j2*16*RST + ks*32 + b_lane);
            }
            #pragma unroll
            for (int mi = 0; mi < 2; ++mi)
                #pragma unroll
                for (int j2 = 0; j2 < 2; ++j2)
                    #pragma unroll
                    for (int sub = 0; sub < 2; ++sub) {
                        int ni = j2*2 + sub;
                        mma16816(acc[mi][ni], ah[mi], bh[j2][sub*2], bh[j2][sub*2+1]);
                        mma16816(acc[mi][ni], ah[mi], bl[j2][sub*2], bl[j2][sub*2+1]);
                        mma16816(acc[mi][ni], al[mi], bh[j2][sub*2], bh[j2][sub*2+1]);
                    }
        }
        __syncthreads();
    }
}

// Fused Q/K/V projections: blockIdx.x selects (tensor, n-block).
struct QkvArgs {
    const bf16 *Ah[3], *Al[3], *Wh[3], *Wl[3];
    const float* bias[3];
    bf16 *Ch[3], *Cl[3];
};

__global__ __launch_bounds__(256, 2) void gemm_qkv(QkvArgs p, int M, int N, int K)
{
    extern __shared__ char sm[];
    const uint32_t sb = smem_u32(sm);

    const int tid  = threadIdx.x;
    const int lane = tid & 31;
    const int wid  = tid >> 5;
    const int wr   = wid >> 1;
    const int wc   = wid & 1;
    const int sel  = blockIdx.x >> 4;
    const int n0   = (blockIdx.x & 15) * 64;
    const int m0   = blockIdx.y * 128;

    const int r  = tid >> 2;
    const int sg = (tid & 3) * 16;
    const char* gAh = (const char*)(p.Ah[sel] + (size_t)(m0 + r) * K) + sg;
    const char* gAl = (const char*)(p.Al[sel] + (size_t)(m0 + r) * K) + sg;
    const char* gWh = (const char*)(p.Wh[sel] + (size_t)(n0 + r) * K) + sg;
    const char* gWl = (const char*)(p.Wl[sel] + (size_t)(n0 + r) * K) + sg;
    const size_t aRowHalf = (size_t)64 * K * 2;

    const uint32_t a_lane = (uint32_t)((wr*32 + (lane & 15)) * RST + (lane >> 4) * 16);
    const uint32_t b_lane = (uint32_t)((wc*32 + (lane & 7) + ((lane >> 4) & 1) * 8) * RST
                                       + ((lane >> 3) & 1) * 16);

    float acc[2][4][4];
    #pragma unroll
    for (int mi = 0; mi < 2; mi++)
        #pragma unroll
        for (int ni = 0; ni < 4; ni++)
            #pragma unroll
            for (int rr = 0; rr < 4; rr++) acc[mi][ni][rr] = 0.0f;

    gemm_mainloop(sb, r, sg, aRowHalf, gAh, gAl, gWh, gWl, a_lane, b_lane, acc, K);

    const float* bias = p.bias[sel];
    bf16* Ch = p.Ch[sel];
    bf16* Cl = p.Cl[sel];
    #pragma unroll
    for (int mi = 0; mi < 2; ++mi) {
        int rr = m0 + wr*32 + mi*16 + (lane >> 2);
        #pragma unroll
        for (int ni = 0; ni < 4; ++ni) {
            int ccol = n0 + wc*32 + ni*8 + (lane & 3) * 2;
            float2 bb = *(const float2*)&bias[ccol];
            uint32_t hi, lo;
            pack_split(acc[mi][ni][0] + bb.x, acc[mi][ni][1] + bb.y, hi, lo);
            *(uint32_t*)&Ch[(size_t)rr * N + ccol] = hi;
            *(uint32_t*)&Cl[(size_t)rr * N + ccol] = lo;
            pack_split(acc[mi][ni][2] + bb.x, acc[mi][ni][3] + bb.y, hi, lo);
            *(uint32_t*)&Ch[(size_t)(rr + 8) * N + ccol] = hi;
            *(uint32_t*)&Cl[(size_t)(rr + 8) * N + ccol] = lo;
        }
    }
}

// Output projection: fp32 out.
__global__ __launch_bounds__(256, 2) void gemm_out(
    const bf16* __restrict__ Ah, const bf16* __restrict__ Al,
    const bf16* __restrict__ Wh, const bf16* __restrict__ Wl,
    const float* __restrict__ bias, float* __restrict__ C,
    int M, int N, int K)
{
    extern __shared__ char sm[];
    const uint32_t sb = smem_u32(sm);

    const int tid  = threadIdx.x;
    const int lane = tid & 31;
    const int wid  = tid >> 5;
    const int wr   = wid >> 1;
    const int wc   = wid & 1;
    const int m0   = blockIdx.y * 128;
    const int n0   = blockIdx.x * 64;

    const int r  = tid >> 2;
    const int sg = (tid & 3) * 16;
    const char* gAh = (const char*)(Ah + (size_t)(m0 + r) * K) + sg;
    const char* gAl = (const char*)(Al + (size_t)(m0 + r) * K) + sg;
    const char* gWh = (const char*)(Wh + (size_t)(n0 + r) * K) + sg;
    const char* gWl = (const char*)(Wl + (size_t)(n0 + r) * K) + sg;
    const size_t aRowHalf = (size_t)64 * K * 2;

    const uint32_t a_lane = (uint32_t)((wr*32 + (lane & 15)) * RST + (lane >> 4) * 16);
    const uint32_t b_lane = (uint32_t)((wc*32 + (lane & 7) + ((lane >> 4) & 1) * 8) * RST
                                       + ((lane >> 3) & 1) * 16);

    float acc[2][4][4];
    #pragma unroll
    for (int mi = 0; mi < 2; mi++)
        #pragma unroll
        for (int ni = 0; ni < 4; ni++)
            #pragma unroll
            for (int rr = 0; rr < 4; rr++) acc[mi][ni][rr] = 0.0f;

    gemm_mainloop(sb, r, sg, aRowHalf, gAh, gAl, gWh, gWl, a_lane, b_lane, acc, K);

    #pragma unroll
    for (int mi = 0; mi < 2; ++mi) {
        int rr = m0 + wr*32 + mi*16 + (lane >> 2);
        #pragma unroll
        for (int ni = 0; ni < 4; ++ni) {
            int ccol = n0 + wc*32 + ni*8 + (lane & 3) * 2;
            float2 bb = *(const float2*)&bias[ccol];
            float2 o0, o1;
            o0.x = acc[mi][ni][0] + bb.x;
            o0.y = acc[mi][ni][1] + bb.y;
            o1.x = acc[mi][ni][2] + bb.x;
            o1.y = acc[mi][ni][3] + bb.y;
            *(float2*)&C[(size_t)rr * N + ccol] = o0;
            *(float2*)&C[(size_t)(rr + 8) * N + ccol] = o1;
        }
    }
}

// ===========================================================================
// HMMA flash attention, split-bf16, double-buffered cp.async K/V tiles.
// Block: 128 queries x (b,h); 8 warps; warp owns 16 query rows.
// ===========================================================================
#define ART 144
#define AQH 0
#define AQL (128*ART)                 // 18432
#define AKV (2*128*ART)               // 36864 : start of KV stages
#define KVS (4*64*ART)                // 36864 : one stage (KH,KL,VH,VL)
#define KH_O 0
#define KL_O (64*ART)
#define VH_O (2*64*ART)
#define VL_O (3*64*ART)
#define AMSK (AKV + 2*KVS)            // 110592
#define ATTN_SMEM (AMSK + 512)        // 111104

__global__ __launch_bounds__(256, 2) void attn_hmma(const int* __restrict__ mask)
{
    extern __shared__ char sm[];
    const uint32_t sb = smem_u32(sm);

    const int tid  = threadIdx.x;
    const int lane = tid & 31;
    const int wid  = tid >> 5;
    const int bh   = blockIdx.y;
    const int b    = bh >> 4;
    const int h    = bh & 15;
    const int q0   = blockIdx.x * 128;

    const int krow = tid >> 2;
    const int ksg  = tid & 3;

    // issue cp.async loads for K/V tile t into stage st (0/1) + mask
    auto issue_kv = [&](int t, int st) {
        const uint32_t s0 = sb + AKV + (uint32_t)st * KVS;
        const size_t base = (size_t)(b*S_ + t*64 + krow) * DM + h*DKH;
        #pragma unroll
        for (int u = 0; u < 2; ++u) {
            int idx = ksg*2 + u;
            cp16(s0 + KH_O + krow*ART + idx*16, g_pkh + base + idx*8);
            cp16(s0 + KL_O + krow*ART + idx*16, g_pkl + base + idx*8);
            cp16(s0 + VH_O + krow*ART + idx*16, g_pvh + base + idx*8);
            cp16(s0 + VL_O + krow*ART + idx*16, g_pvl + base + idx*8);
        }
        if (tid < 64)
            ((float*)(sm + AMSK))[st*64 + tid] = mask[b*S_ + t*64 + tid] ? 0.0f : -1e9f;
    };

    // prologue: stage Q (sync loads) + first KV tile (async)
    issue_kv(0, 0);
    CP_COMMIT();
    {
        const int row = tid >> 1;
        const int hf  = (tid & 1) * 4;
        const size_t qb = (size_t)(b*S_ + q0 + row) * DM + h*DKH;
        #pragma unroll
        for (int u = 0; u < 4; ++u) {
            int idx = hf + u;
            *(uint4*)(sm + AQH + row*ART + idx*16) = *(const uint4*)(g_pqh + qb + idx*8);
            *(uint4*)(sm + AQL + row*ART + idx*16) = *(const uint4*)(g_pql + qb + idx*8);
        }
    }

    const uint32_t q_lane = (uint32_t)((wid*16 + (lane & 15)) * ART + (lane >> 4) * 16);
    const uint32_t b_lane = (uint32_t)(((lane & 7) + ((lane >> 4) & 1) * 8) * ART
                                       + ((lane >> 3) & 1) * 16);
    const uint32_t v_lane = (uint32_t)((lane & 15) * ART + (lane >> 4) * 16);

    float o[8][4];
    #pragma unroll
    for (int ni = 0; ni < 8; ni++)
        #pragma unroll
        for (int rr = 0; rr < 4; rr++) o[ni][rr] = 0.0f;
    float m0 = -1e30f, m1 = -1e30f, l0 = 0.0f, l1 = 0.0f;

    for (int t = 0; t < S_/64; ++t) {
        const int st = t & 1;
        __syncthreads();   // all warps done computing on stage st^1
        if (t + 1 < S_/64) {
            issue_kv(t + 1, st ^ 1);
            CP_COMMIT();
            CP_WAIT1();
        } else {
            CP_WAIT0();
        }
        __syncthreads();   // stage st ready

        const uint32_t kvb = sb + AKV + (uint32_t)st * KVS;
        const float* maskf = (const float*)(sm + AMSK) + st*64;

        // ---- S = Q K^T (3-term split) ----
        float s[8][4];
        #pragma unroll
        for (int ni = 0; ni < 8; ni++)
            #pragma unroll
            for (int rr = 0; rr < 4; rr++) s[ni][rr] = 0.0f;

        #pragma unroll
        for (int kt = 0; kt < 4; ++kt) {
            uint32_t qh[4], ql[4];
            ldsm4(qh, sb + AQH + kt*32 + q_lane);
            ldsm4(ql, sb + AQL + kt*32 + q_lane);
            #pragma unroll
            for (int j2 = 0; j2 < 4; ++j2) {
                uint32_t kh[4], kl[4];
                ldsm4(kh, kvb + KH_O + j2*16*ART + kt*32 + b_lane);
                ldsm4(kl, kvb + KL_O + j2*16*ART + kt*32 + b_lane);
                #pragma unroll
                for (int sub = 0; sub < 2; ++sub) {
                    int ni = j2*2 + sub;
                    mma16816(s[ni], qh, kh[sub*2], kh[sub*2+1]);
                    mma16816(s[ni], qh, kl[sub*2], kl[sub*2+1]);
                    mma16816(s[ni], ql, kh[sub*2], kh[sub*2+1]);
                }
            }
        }

        // ---- scale + mask + online softmax ----
        float mx0 = -1e30f, mx1 = -1e30f;
        #pragma unroll
        for (int ni = 0; ni < 8; ++ni) {
            float2 mv = *(const float2*)&maskf[ni*8 + (lane & 3)*2];
            s[ni][0] = fmaf(s[ni][0], 0.125f, mv.x);
            s[ni][1] = fmaf(s[ni][1], 0.125f, mv.y);
            s[ni][2] = fmaf(s[ni][2], 0.125f, mv.x);
            s[ni][3] = fmaf(s[ni][3], 0.125f, mv.y);
            mx0 = fmaxf(mx0, fmaxf(s[ni][0], s[ni][1]));
            mx1 = fmaxf(mx1, fmaxf(s[ni][2], s[ni][3]));
        }
        mx0 = fmaxf(mx0, __shfl_xor_sync(0xffffffffu, mx0, 1));
        mx0 = fmaxf(mx0, __shfl_xor_sync(0xffffffffu, mx0, 2));
        mx1 = fmaxf(mx1, __shfl_xor_sync(0xffffffffu, mx1, 1));
        mx1 = fmaxf(mx1, __shfl_xor_sync(0xffffffffu, mx1, 2));
        float m0n = fmaxf(m0, mx0);
        float m1n = fmaxf(m1, mx1);
        float c0 = __expf(m0 - m0n);
        float c1 = __expf(m1 - m1n);
        float sum0 = 0.0f, sum1 = 0.0f;
        #pragma unroll
        for (int ni = 0; ni < 8; ++ni) {
            s[ni][0] = __expf(s[ni][0] - m0n);
            s[ni][1] = __expf(s[ni][1] - m0n);
            s[ni][2] = __expf(s[ni][2] - m1n);
            s[ni][3] = __expf(s[ni][3] - m1n);
            sum0 += s[ni][0] + s[ni][1];
            sum1 += s[ni][2] + s[ni][3];
        }
        sum0 += __shfl_xor_sync(0xffffffffu, sum0, 1);
        sum0 += __shfl_xor_sync(0xffffffffu, sum0, 2);
        sum1 += __shfl_xor_sync(0xffffffffu, sum1, 1);
        sum1 += __shfl_xor_sync(0xffffffffu, sum1, 2);
        l0 = l0 * c0 + sum0;
        l1 = l1 * c1 + sum1;
        m0 = m0n; m1 = m1n;
        #pragma unroll
        for (int ni = 0; ni < 8; ++ni) {
            o[ni][0] *= c0; o[ni][1] *= c0;
            o[ni][2] *= c1; o[ni][3] *= c1;
        }

        // ---- O += P V ----
        #pragma unroll
        for (int kt = 0; kt < 4; ++kt) {
            uint32_t pah[4], pal[4];
            pack_split(s[2*kt][0],   s[2*kt][1],   pah[0], pal[0]);
            pack_split(s[2*kt][2],   s[2*kt][3],   pah[1], pal[1]);
            pack_split(s[2*kt+1][0], s[2*kt+1][1], pah[2], pal[2]);
            pack_split(s[2*kt+1][2], s[2*kt+1][3], pah[3], pal[3]);
            #pragma unroll
            for (int jp = 0; jp < 4; ++jp) {
                uint32_t vh[4], vl[4];
                ldsm4t(vh, kvb + VH_O + kt*16*ART + jp*32 + v_lane);
                ldsm4t(vl, kvb + VL_O + kt*16*ART + jp*32 + v_lane);
                #pragma unroll
                for (int sub = 0; sub < 2; ++sub) {
                    int ni = jp*2 + sub;
                    mma16816(o[ni], pah, vh[sub*2], vh[sub*2+1]);
                    mma16816(o[ni], pah, vl[sub*2], vl[sub*2+1]);
                    mma16816(o[ni], pal, vh[sub*2], vh[sub*2+1]);
                }
            }
        }
    }

    // ---- epilogue: normalize, write ctx split-bf16 ----
    const float inv0 = 1.0f / l0;
    const float inv1 = 1.0f / l1;
    const int r0 = q0 + wid*16 + (lane >> 2);
    #pragma unroll
    for (int ni = 0; ni < 8; ++ni) {
        int col = h*DKH + ni*8 + (lane & 3)*2;
        uint32_t hi, lo;
        size_t e0 = (size_t)(b*S_ + r0) * DM + col;
        size_t e1 = (size_t)(b*S_ + r0 + 8) * DM + col;
        pack_split(o[ni][0] * inv0, o[ni][1] * inv0, hi, lo);
        *(uint32_t*)&g_ch[e0] = hi;
        *(uint32_t*)&g_cl[e0] = lo;
        pack_split(o[ni][2] * inv1, o[ni][3] * inv1, hi, lo);
        *(uint32_t*)&g_ch[e1] = hi;
        *(uint32_t*)&g_cl[e1] = lo;
    }
}

// ---------------------------------------------------------------------------
extern "C" void kernel_launch(void* const* d_in, const int* in_sizes, int n_in,
                              void* d_out, int out_size)
{
    const float* q    = (const float*)d_in[0];
    const float* k    = (const float*)d_in[1];
    const float* v    = (const float*)d_in[2];
    const int*   mask = (const int*)  d_in[3];
    const float* Wq   = (const float*)d_in[4];
    const float* bq   = (const float*)d_in[5];
    const float* Wk   = (const float*)d_in[6];
    const float* bk   = (const float*)d_in[7];
    const float* Wv   = (const float*)d_in[8];
    const float* bv   = (const float*)d_in[9];
    const float* Wo   = (const float*)d_in[10];
    const float* bo   = (const float*)d_in[11];
    float* out = (float*)d_out;

    bf16 *qh, *ql, *kh, *kl, *vh, *vl;
    bf16 *wqh, *wql, *wkh, *wkl, *wvh, *wvl, *woh, *wol;
    bf16 *pqh, *pql, *pkh, *pkl, *pvh, *pvl, *ch, *cl;
    cudaGetSymbolAddress((void**)&qh, g_qh);   cudaGetSymbolAddress((void**)&ql, g_ql);
    cudaGetSymbolAddress((void**)&kh, g_kh);   cudaGetSymbolAddress((void**)&kl, g_kl);
    cudaGetSymbolAddress((void**)&vh, g_vh);   cudaGetSymbolAddress((void**)&vl, g_vl);
    cudaGetSymbolAddress((void**)&wqh, g_wqh); cudaGetSymbolAddress((void**)&wql, g_wql);
    cudaGetSymbolAddress((void**)&wkh, g_wkh); cudaGetSymbolAddress((void**)&wkl, g_wkl);
    cudaGetSymbolAddress((void**)&wvh, g_wvh); cudaGetSymbolAddress((void**)&wvl, g_wvl);
    cudaGetSymbolAddress((void**)&woh, g_woh); cudaGetSymbolAddress((void**)&wol, g_wol);
    cudaGetSymbolAddress((void**)&pqh, g_pqh); cudaGetSymbolAddress((void**)&pql, g_pql);
    cudaGetSymbolAddress((void**)&pkh, g_pkh); cudaGetSymbolAddress((void**)&pkl, g_pkl);
    cudaGetSymbolAddress((void**)&pvh, g_pvh); cudaGetSymbolAddress((void**)&pvl, g_pvl);
    cudaGetSymbolAddress((void**)&ch, g_ch);   cudaGetSymbolAddress((void**)&cl, g_cl);

    cudaFuncSetAttribute(gemm_qkv, cudaFuncAttributeMaxDynamicSharedMemorySize, GEMM_SMEM);
    cudaFuncSetAttribute(gemm_out, cudaFuncAttributeMaxDynamicSharedMemorySize, GEMM_SMEM);
    cudaFuncSetAttribute(attn_hmma, cudaFuncAttributeMaxDynamicSharedMemorySize, ATTN_SMEM);

    // 1) prep: split inputs (3 tensors) + weights (4 tensors)
    const int NI4 = MR*DM/4, NW4 = DM*DM/4;
    PrepArgs pin;
    pin.in[0] = q;  pin.hi[0] = qh;  pin.lo[0] = ql;
    pin.in[1] = k;  pin.hi[1] = kh;  pin.lo[1] = kl;
    pin.in[2] = v;  pin.hi[2] = vh;  pin.lo[2] = vl;
    pin.in[3] = q;  pin.hi[3] = qh;  pin.lo[3] = ql;   // unused slot
    prep_split_n<<<dim3(NI4/256, 3), 256>>>(pin, NI4);
    PrepArgs pw;
    pw.in[0] = Wq; pw.hi[0] = wqh; pw.lo[0] = wql;
    pw.in[1] = Wk; pw.hi[1] = wkh; pw.lo[1] = wkl;
    pw.in[2] = Wv; pw.hi[2] = wvh; pw.lo[2] = wvl;
    pw.in[3] = Wo; pw.hi[3] = woh; pw.lo[3] = wol;
    prep_split_n<<<dim3(NW4/256, 4), 256>>>(pw, NW4);

    // 2) fused Q/K/V projections (split-bf16 output)
    QkvArgs pq;
    pq.Ah[0] = qh; pq.Al[0] = ql; pq.Wh[0] = wqh; pq.Wl[0] = wql;
    pq.bias[0] = bq; pq.Ch[0] = pqh; pq.Cl[0] = pql;
    pq.Ah[1] = kh; pq.Al[1] = kl; pq.Wh[1] = wkh; pq.Wl[1] = wkl;
    pq.bias[1] = bk; pq.Ch[1] = pkh; pq.Cl[1] = pkl;
    pq.Ah[2] = vh; pq.Al[2] = vl; pq.Wh[2] = wvh; pq.Wl[2] = wvl;
    pq.bias[2] = bv; pq.Ch[2] = pvh; pq.Cl[2] = pvl;
    gemm_qkv<<<dim3(3*DM/64, MR/128), 256, GEMM_SMEM>>>(pq, MR, DM, DM);

    // 3) attention (reads split proj, writes split ctx)
    attn_hmma<<<dim3(S_/128, B_*NH), 256, ATTN_SMEM>>>(mask);

    // 4) output projection (fp32 out)
    gemm_out<<<dim3(DM/64, MR/128), 256, GEMM_SMEM>>>(ch, cl, woh, wol, bo, out, MR, DM, DM);
}